// round 10
// baseline (speedup 1.0000x reference)
#include <cuda_runtime.h>
#include <cstdint>
#include <math.h>

#define D_MODEL 1024
#define NHEAD 16
#define HEAD_DIM 64
#define BATCH 2
#define SEQ 2048
#define MTOT (BATCH*SEQ)   // 4096

// Scratch (allocation-free rule: __device__ globals)
__device__ float g_Q[MTOT * D_MODEL];
__device__ float g_K[MTOT * D_MODEL];
__device__ float g_V[MTOT * D_MODEL];
__device__ float g_Attn[MTOT * D_MODEL];

// ---------------------------------------------------------------------------
// helpers
// ---------------------------------------------------------------------------
__device__ __forceinline__ unsigned f2tf(float x) {
    unsigned u;
    asm("cvt.rna.tf32.f32 %0, %1;" : "=r"(u) : "f"(x));
    return u;
}
__device__ __forceinline__ float f2tff(float x) { return __uint_as_float(f2tf(x)); }
__device__ __forceinline__ unsigned cvtu(unsigned r) { return f2tf(__uint_as_float(r)); }

__device__ __forceinline__ void mma8(float* c, const unsigned* a,
                                     unsigned b0, unsigned b1) {
    asm volatile(
        "mma.sync.aligned.m16n8k8.row.col.f32.tf32.tf32.f32 "
        "{%0,%1,%2,%3}, {%4,%5,%6,%7}, {%8,%9}, {%0,%1,%2,%3};"
        : "+f"(c[0]), "+f"(c[1]), "+f"(c[2]), "+f"(c[3])
        : "r"(a[0]), "r"(a[1]), "r"(a[2]), "r"(a[3]), "r"(b0), "r"(b1));
}

// ldmatrix x4: 4 8x8 b16 matrices; for tf32 each 32-bit result = one fp32 elem.
__device__ __forceinline__ void ldsm4(unsigned& r0, unsigned& r1,
                                      unsigned& r2, unsigned& r3, const void* p) {
    unsigned addr = (unsigned)__cvta_generic_to_shared(p);
    asm volatile("ldmatrix.sync.aligned.m8n8.x4.shared.b16 {%0,%1,%2,%3}, [%4];"
        : "=r"(r0), "=r"(r1), "=r"(r2), "=r"(r3) : "r"(addr));
}

__device__ __forceinline__ void cp_async16(void* dst, const void* src) {
    unsigned int d = (unsigned int)__cvta_generic_to_shared(dst);
    asm volatile("cp.async.cg.shared.global [%0], [%1], 16;" :: "r"(d), "l"(src));
}
#define CP_COMMIT() asm volatile("cp.async.commit_group;")
#define CP_WAIT1()  asm volatile("cp.async.wait_group 1;")

// ---------------------------------------------------------------------------
// tf32 GEMM, 3-stage cp.async, one sync per k-tile:
//   C = (A @ W^T + bias) * scale   [tf32-round output if ROUND]
// Operands rounded to tf32 AT THE FRAGMENT (post-ldmatrix) — bit-identical
// to staging-side rounding but 10x fewer cvts.
// 128x128 block, BK=32, 8 warps (2x4), warp tile 64x32, mma.m16n8k8.
// smem stride 36 -> every ldmatrix phase conflict-free.
// ---------------------------------------------------------------------------
#define AS2 36
#define GEMM_SMEM (6 * 128 * AS2 * (int)sizeof(float))   // 110592 bytes

template<bool ROUND>
__global__ __launch_bounds__(256, 2) void gemm_mma(
    const float* __restrict__ A, const float* __restrict__ W,
    const float* __restrict__ bias, float scale, float* __restrict__ C)
{
    extern __shared__ float sm[];
    float* As = sm;                   // [3][128*AS2]
    float* Ws = sm + 3 * 128 * AS2;   // [3][128*AS2]

    const int m0 = blockIdx.y * 128;
    const int n0 = blockIdx.x * 128;
    const int t  = threadIdx.x;
    const int wid = t >> 5, lane = t & 31;
    const int g4 = lane >> 2, q4 = lane & 3;
    const int wm = wid >> 2;          // 0..1
    const int wn = wid & 3;           // 0..3
    const int lrow = t >> 1;          // 0..127
    const int lseg = (t & 1) * 16;

    float c[4][4][4];
    #pragma unroll
    for (int i = 0; i < 4; i++)
        #pragma unroll
        for (int j = 0; j < 4; j++)
            c[i][j][0] = c[i][j][1] = c[i][j][2] = c[i][j][3] = 0.f;

    const float* Ap = A + (size_t)(m0 + lrow) * D_MODEL + lseg;
    const float* Wp = W + (size_t)(n0 + lrow) * D_MODEL + lseg;

    // ldmatrix per-lane address components
    const int aoff = (lane & 15) * AS2 + (lane >> 4) * 4;                          // A/x4
    const int boff = ((lane & 7) + (lane >> 4) * 8) * AS2 + ((lane >> 3) & 1) * 4; // B-pair/x4

    const int NKT = D_MODEL / 32;

    // prologue: stage tiles 0 and 1
    #pragma unroll
    for (int s = 0; s < 2; s++) {
        float* Ab = As + s * 128 * AS2;
        float* Wb = Ws + s * 128 * AS2;
        const int k0 = s * 32;
        #pragma unroll
        for (int i = 0; i < 4; i++) {
            cp_async16(&Ab[lrow * AS2 + lseg + i * 4], Ap + k0 + i * 4);
            cp_async16(&Wb[lrow * AS2 + lseg + i * 4], Wp + k0 + i * 4);
        }
        CP_COMMIT();
    }

    int buf = 0;
    for (int kt = 0; kt < NKT; kt++) {
        CP_WAIT1();          // tile kt resident (kt+1 may still be in flight)
        __syncthreads();     // visibility + protects buf being refilled below

        // stage tile kt+2 into buffer (kt+2)%3 (its readers finished at kt-1)
        if (kt + 2 < NKT) {
            const int nb = (buf + 2 >= 3) ? buf - 1 : buf + 2;
            float* Ab = As + nb * 128 * AS2;
            float* Wb = Ws + nb * 128 * AS2;
            const int k0 = (kt + 2) * 32;
            #pragma unroll
            for (int i = 0; i < 4; i++) {
                cp_async16(&Ab[lrow * AS2 + lseg + i * 4], Ap + k0 + i * 4);
                cp_async16(&Wb[lrow * AS2 + lseg + i * 4], Wp + k0 + i * 4);
            }
        }
        CP_COMMIT();

        // compute from buf; fragments via ldmatrix, tf32 rounding at fragment
        const float* aB = As + buf * 128 * AS2 + (wm * 64) * AS2 + aoff;
        const float* bB = Ws + buf * 128 * AS2 + (wn * 32) * AS2 + boff;
        #pragma unroll
        for (int kk = 0; kk < 4; kk++) {
            unsigned a[4][4];
            #pragma unroll
            for (int i = 0; i < 4; i++) {
                ldsm4(a[i][0], a[i][1], a[i][2], a[i][3],
                      aB + i * 16 * AS2 + kk * 8);
                a[i][0] = cvtu(a[i][0]); a[i][1] = cvtu(a[i][1]);
                a[i][2] = cvtu(a[i][2]); a[i][3] = cvtu(a[i][3]);
            }
            unsigned rb[8];
            ldsm4(rb[0], rb[1], rb[2], rb[3], bB + kk * 8);             // j=0,1
            ldsm4(rb[4], rb[5], rb[6], rb[7], bB + 16 * AS2 + kk * 8);  // j=2,3
            #pragma unroll
            for (int e = 0; e < 8; e++) rb[e] = cvtu(rb[e]);
            #pragma unroll
            for (int j = 0; j < 4; j++) {
                #pragma unroll
                for (int i = 0; i < 4; i++)
                    mma8(c[i][j], a[i], rb[j * 2], rb[j * 2 + 1]);
            }
        }
        buf = (buf + 1 == 3) ? 0 : buf + 1;
    }

    // ---- epilogue: direct STG from fragments, bias in registers ----
    #pragma unroll
    for (int j = 0; j < 4; j++) {
        const int col = n0 + wn * 32 + j * 8 + 2 * q4;
        const float2 bb = *(const float2*)&bias[col];
        #pragma unroll
        for (int i = 0; i < 4; i++) {
            const int row = m0 + wm * 64 + i * 16 + g4;
            float2 v0, v1;
            v0.x = (c[i][j][0] + bb.x) * scale;
            v0.y = (c[i][j][1] + bb.y) * scale;
            v1.x = (c[i][j][2] + bb.x) * scale;
            v1.y = (c[i][j][3] + bb.y) * scale;
            if (ROUND) {
                v0.x = f2tff(v0.x); v0.y = f2tff(v0.y);
                v1.x = f2tff(v1.x); v1.y = f2tff(v1.y);
            }
            *(float2*)&C[(size_t)row * D_MODEL + col] = v0;
            *(float2*)&C[(size_t)(row + 8) * D_MODEL + col] = v1;
        }
    }
}

// ---------------------------------------------------------------------------
// Flash attention, mma.sync m16n8k8 tf32, register accumulators.
// Q/K/V arrive tf32-pre-rounded. K and P fragments loaded via ldmatrix.
// ---------------------------------------------------------------------------
#define KS 68
#define VS 72
#define PS 68
#define NTILES (SEQ / 64)
#define ATTN_SMEM ((128*PS + 2*64*KS + 2*64*VS) * (int)sizeof(float))  // 106496

__global__ __launch_bounds__(256, 2) void attn_mma(
    const float* __restrict__ Qb, const float* __restrict__ Kb,
    const float* __restrict__ Vb, float* __restrict__ Ob)
{
    extern __shared__ float sm[];
    float* Ps = sm;                         // [128][PS]  (Q staging, then P)
    float* Kbuf = Ps + 128 * PS;            // [2][64][KS]
    float* Vbuf = Kbuf + 2 * 64 * KS;       // [2][64][VS]

    const int qt = blockIdx.x, h = blockIdx.y, b = blockIdx.z;
    const int t = threadIdx.x, w = t >> 5, lane = t & 31;
    const int g4 = lane >> 2, q4 = lane & 3;
    const int base_q = b * SEQ + qt * 128;
    const int hcol = h * HEAD_DIM;

    // ldmatrix per-lane address components
    const int koff = ((lane & 7) + (lane >> 4) * 8) * KS + ((lane >> 3) & 1) * 4;  // K-pair
    const int poff = (lane & 15) * PS + (lane >> 4) * 4;                            // P/x4

    // --- stage tile 0 of K/V via cp.async ---
    {
        const int base_k = b * SEQ;
        #pragma unroll
        for (int i = 0; i < 4; i++) {
            const int id = t + i * 256;
            const int row = id >> 4, seg = id & 15;
            const size_t g = (size_t)(base_k + row) * D_MODEL + hcol + seg * 4;
            cp_async16(&Kbuf[row * KS + seg * 4], Kb + g);
            cp_async16(&Vbuf[row * VS + seg * 4], Vb + g);
        }
    }
    CP_COMMIT();

    // --- stage Q and load A-fragments (already tf32 bit patterns) ---
    {
        const int r = t >> 1;
        const int c0 = (t & 1) * 32;
        #pragma unroll
        for (int i = 0; i < 8; i++)
            *(float4*)&Ps[r * PS + c0 + i * 4] =
                *(const float4*)&Qb[(size_t)(base_q + r) * D_MODEL + hcol + c0 + i * 4];
    }
    __syncwarp();

    unsigned qa[8][4];
    {
        const float* qB = Ps + (w * 16) * PS + poff;
        #pragma unroll
        for (int kk = 0; kk < 8; kk++)
            ldsm4(qa[kk][0], qa[kk][1], qa[kk][2], qa[kk][3], qB + kk * 8);
    }
    __syncwarp();   // Ps free for P reuse

    float of[8][4];
    #pragma unroll
    for (int n = 0; n < 8; n++)
        of[n][0] = of[n][1] = of[n][2] = of[n][3] = 0.f;
    float m0r = -1e30f, m1r = -1e30f, l0r = 0.f, l1r = 0.f;

    for (int jt = 0; jt < NTILES; jt++) {
        float* Kc = Kbuf + (jt & 1) * 64 * KS;
        float* Vc = Vbuf + (jt & 1) * 64 * VS;

        if (jt + 1 < NTILES) {
            float* Kn = Kbuf + ((jt + 1) & 1) * 64 * KS;
            float* Vn = Vbuf + ((jt + 1) & 1) * 64 * VS;
            const int base_k = b * SEQ + (jt + 1) * 64;
            #pragma unroll
            for (int i = 0; i < 4; i++) {
                const int id = t + i * 256;
                const int row = id >> 4, seg = id & 15;
                const size_t g = (size_t)(base_k + row) * D_MODEL + hcol + seg * 4;
                cp_async16(&Kn[row * KS + seg * 4], Kb + g);
                cp_async16(&Vn[row * VS + seg * 4], Vb + g);
            }
        }
        CP_COMMIT();
        CP_WAIT1();          // tile jt resident; jt+1 in flight
        __syncthreads();

        // ---- S = Q @ K^T  (K fragments via ldmatrix, 2 n-blocks per op) ----
        float sfr[8][4];
        #pragma unroll
        for (int n = 0; n < 8; n++)
            sfr[n][0] = sfr[n][1] = sfr[n][2] = sfr[n][3] = 0.f;
        {
            const float* kB = Kc + koff;
            #pragma unroll
            for (int kk = 0; kk < 8; kk++) {
                #pragma unroll
                for (int jp = 0; jp < 4; jp++) {
                    unsigned rb[4];
                    ldsm4(rb[0], rb[1], rb[2], rb[3], kB + jp * 16 * KS + kk * 8);
                    mma8(sfr[jp * 2],     qa[kk], rb[0], rb[1]);
                    mma8(sfr[jp * 2 + 1], qa[kk], rb[2], rb[3]);
                }
            }
        }

        // ---- online softmax in registers ----
        float mx0 = -1e30f, mx1 = -1e30f;
        #pragma unroll
        for (int n = 0; n < 8; n++) {
            mx0 = fmaxf(mx0, fmaxf(sfr[n][0], sfr[n][1]));
            mx1 = fmaxf(mx1, fmaxf(sfr[n][2], sfr[n][3]));
        }
        mx0 = fmaxf(mx0, __shfl_xor_sync(0xffffffffu, mx0, 1));
        mx0 = fmaxf(mx0, __shfl_xor_sync(0xffffffffu, mx0, 2));
        mx1 = fmaxf(mx1, __shfl_xor_sync(0xffffffffu, mx1, 1));
        mx1 = fmaxf(mx1, __shfl_xor_sync(0xffffffffu, mx1, 2));

        const float mn0 = fmaxf(m0r, mx0);
        const float mn1 = fmaxf(m1r, mx1);
        const float a0 = __expf(m0r - mn0);
        const float a1 = __expf(m1r - mn1);
        m0r = mn0; m1r = mn1;

        float s0 = 0.f, s1 = 0.f;
        #pragma unroll
        for (int n = 0; n < 8; n++) {
            sfr[n][0] = __expf(sfr[n][0] - mn0);
            sfr[n][1] = __expf(sfr[n][1] - mn0);
            sfr[n][2] = __expf(sfr[n][2] - mn1);
            sfr[n][3] = __expf(sfr[n][3] - mn1);
            s0 += sfr[n][0] + sfr[n][1];
            s1 += sfr[n][2] + sfr[n][3];
            of[n][0] *= a0; of[n][1] *= a0;
            of[n][2] *= a1; of[n][3] *= a1;
            *(float2*)&Ps[(w * 16 + g4)     * PS + n * 8 + 2 * q4] =
                make_float2(sfr[n][0], sfr[n][1]);
            *(float2*)&Ps[(w * 16 + g4 + 8) * PS + n * 8 + 2 * q4] =
                make_float2(sfr[n][2], sfr[n][3]);
        }
        s0 += __shfl_xor_sync(0xffffffffu, s0, 1);
        s0 += __shfl_xor_sync(0xffffffffu, s0, 2);
        s1 += __shfl_xor_sync(0xffffffffu, s1, 1);
        s1 += __shfl_xor_sync(0xffffffffu, s1, 2);
        l0r = l0r * a0 + s0;
        l1r = l1r * a1 + s1;
        __syncwarp();

        // ---- O += P @ V  (P fragments via ldmatrix + cvt) ----
        {
            const float* pB = Ps + (w * 16) * PS + poff;
            #pragma unroll
            for (int kk = 0; kk < 8; kk++) {
                unsigned r0, r1, r2, r3;
                ldsm4(r0, r1, r2, r3, pB + kk * 8);
                unsigned pa[4];
                pa[0] = cvtu(r0); pa[1] = cvtu(r1);
                pa[2] = cvtu(r2); pa[3] = cvtu(r3);
                #pragma unroll
                for (int n = 0; n < 8; n++) {
                    unsigned b0 = __float_as_uint(Vc[(kk * 8 + q4)     * VS + n * 8 + g4]);
                    unsigned b1 = __float_as_uint(Vc[(kk * 8 + q4 + 4) * VS + n * 8 + g4]);
                    mma8(of[n], pa, b0, b1);
                }
            }
        }
        __syncwarp();
        __syncthreads();   // all warps done with Kc/Vc before restaging
    }

    // ---- epilogue: normalize, write [B,T,H*hd] ----
    const float inv0 = 1.f / l0r;
    const float inv1 = 1.f / l1r;
    const int r0 = base_q + w * 16 + g4;
    #pragma unroll
    for (int n = 0; n < 8; n++) {
        const int c = hcol + n * 8 + 2 * q4;
        *(float2*)&Ob[(size_t)r0 * D_MODEL + c] =
            make_float2(of[n][0] * inv0, of[n][1] * inv0);
        *(float2*)&Ob[(size_t)(r0 + 8) * D_MODEL + c] =
            make_float2(of[n][2] * inv1, of[n][3] * inv1);
    }
}

// ---------------------------------------------------------------------------
extern "C" void kernel_launch(void* const* d_in, const int* in_sizes, int n_in,
                              void* d_out, int out_size)
{
    const float* query = (const float*)d_in[0];
    const float* key   = (const float*)d_in[1];
    const float* value = (const float*)d_in[2];
    const float* Wq    = (const float*)d_in[3];
    const float* bq    = (const float*)d_in[4];
    const float* Wk    = (const float*)d_in[5];
    const float* bk    = (const float*)d_in[6];
    const float* Wv    = (const float*)d_in[7];
    const float* bv    = (const float*)d_in[8];
    const float* Wo    = (const float*)d_in[9];
    const float* bo    = (const float*)d_in[10];
    float* out = (float*)d_out;

    float *pQ, *pK, *pV, *pA;
    cudaGetSymbolAddress((void**)&pQ, g_Q);
    cudaGetSymbolAddress((void**)&pK, g_K);
    cudaGetSymbolAddress((void**)&pV, g_V);
    cudaGetSymbolAddress((void**)&pA, g_Attn);

    cudaFuncSetAttribute(gemm_mma<true>,
                         cudaFuncAttributeMaxDynamicSharedMemorySize, GEMM_SMEM);
    cudaFuncSetAttribute(gemm_mma<false>,
                         cudaFuncAttributeMaxDynamicSharedMemorySize, GEMM_SMEM);
    cudaFuncSetAttribute(attn_mma,
                         cudaFuncAttributeMaxDynamicSharedMemorySize, ATTN_SMEM);

    dim3 gemm_grid(D_MODEL / 128, MTOT / 128);   // (8, 32)
    const float qscale = 0.125f;                 // 1/sqrt(64)

    gemm_mma<true><<<gemm_grid, 256, GEMM_SMEM>>>(query, Wq, bq, qscale, pQ);
    gemm_mma<true><<<gemm_grid, 256, GEMM_SMEM>>>(key,   Wk, bk, 1.f,    pK);
    gemm_mma<true><<<gemm_grid, 256, GEMM_SMEM>>>(value, Wv, bv, 1.f,    pV);

    dim3 attn_grid(SEQ / 128, NHEAD, BATCH);     // (16, 16, 2)
    attn_mma<<<attn_grid, 256, ATTN_SMEM>>>(pQ, pK, pV, pA);

    gemm_mma<false><<<gemm_grid, 256, GEMM_SMEM>>>(pA, Wo, bo, 1.f, out);
}

// round 11
// speedup vs baseline: 1.1197x; 1.1197x over previous
#include <cuda_runtime.h>
#include <cstdint>
#include <math.h>

#define D_MODEL 1024
#define NHEAD 16
#define HEAD_DIM 64
#define BATCH 2
#define SEQ 2048
#define MTOT (BATCH*SEQ)   // 4096

// Scratch (allocation-free rule: __device__ globals)
__device__ float g_Q[MTOT * D_MODEL];
__device__ float g_K[MTOT * D_MODEL];
__device__ float g_Vt[MTOT * D_MODEL];   // V projection, TRANSPOSED: [b][channel][token]
__device__ float g_Attn[MTOT * D_MODEL];

// ---------------------------------------------------------------------------
// helpers
// ---------------------------------------------------------------------------
__device__ __forceinline__ unsigned f2tf(float x) {
    unsigned u;
    asm("cvt.rna.tf32.f32 %0, %1;" : "=r"(u) : "f"(x));
    return u;
}
__device__ __forceinline__ float f2tff(float x) { return __uint_as_float(f2tf(x)); }
__device__ __forceinline__ unsigned cvtu(unsigned r) { return f2tf(__uint_as_float(r)); }

__device__ __forceinline__ void mma8(float* c, const unsigned* a,
                                     unsigned b0, unsigned b1) {
    asm volatile(
        "mma.sync.aligned.m16n8k8.row.col.f32.tf32.tf32.f32 "
        "{%0,%1,%2,%3}, {%4,%5,%6,%7}, {%8,%9}, {%0,%1,%2,%3};"
        : "+f"(c[0]), "+f"(c[1]), "+f"(c[2]), "+f"(c[3])
        : "r"(a[0]), "r"(a[1]), "r"(a[2]), "r"(a[3]), "r"(b0), "r"(b1));
}

// ldmatrix x4: 4 8x8 b16 matrices; for tf32 each 32-bit result = one fp32 elem.
__device__ __forceinline__ void ldsm4(unsigned& r0, unsigned& r1,
                                      unsigned& r2, unsigned& r3, const void* p) {
    unsigned addr = (unsigned)__cvta_generic_to_shared(p);
    asm volatile("ldmatrix.sync.aligned.m8n8.x4.shared.b16 {%0,%1,%2,%3}, [%4];"
        : "=r"(r0), "=r"(r1), "=r"(r2), "=r"(r3) : "r"(addr));
}

__device__ __forceinline__ void cp_async16(void* dst, const void* src) {
    unsigned int d = (unsigned int)__cvta_generic_to_shared(dst);
    asm volatile("cp.async.cg.shared.global [%0], [%1], 16;" :: "r"(d), "l"(src));
}
#define CP_COMMIT() asm volatile("cp.async.commit_group;")
#define CP_WAIT1()  asm volatile("cp.async.wait_group 1;")

// ---------------------------------------------------------------------------
// Hand-rolled tf32 GEMM (R9-proven):  C = (A @ W^T + bias) * scale
// [ROUND: output tf32-rounded]  [TRANSV: output written transposed
//  as [b][channel][token] for the attention V operand]
// 128x128 block, BK=32, 8 warps (2x4), warp tile 64x32, mma.m16n8k8.
// Operands rounded to tf32 at staging (overlapped with LDG wait);
// inner loop = LDSM + HMMA only. smem stride 36 -> conflict-free.
// ---------------------------------------------------------------------------
#define AS2 36
#define GEMM_SMEM (4 * 128 * AS2 * (int)sizeof(float))   // 73728 bytes

template<bool ROUND, bool TRANSV>
__global__ __launch_bounds__(256, 2) void gemm_mma(
    const float* __restrict__ A, const float* __restrict__ W,
    const float* __restrict__ bias, float scale, float* __restrict__ C)
{
    extern __shared__ float sm[];
    float* As = sm;                   // [2][128*AS2]
    float* Ws = sm + 2 * 128 * AS2;   // [2][128*AS2]

    const int m0 = blockIdx.y * 128;
    const int n0 = blockIdx.x * 128;
    const int t  = threadIdx.x;
    const int wid = t >> 5, lane = t & 31;
    const int g4 = lane >> 2, q4 = lane & 3;
    const int wm = wid >> 2;          // 0..1
    const int wn = wid & 3;           // 0..3
    const int lrow = t >> 1;          // 0..127
    const int lseg = (t & 1) * 16;

    float c[4][4][4];
    #pragma unroll
    for (int i = 0; i < 4; i++)
        #pragma unroll
        for (int j = 0; j < 4; j++)
            c[i][j][0] = c[i][j][1] = c[i][j][2] = c[i][j][3] = 0.f;

    const float* Ap = A + (size_t)(m0 + lrow) * D_MODEL + lseg;
    const float* Wp = W + (size_t)(n0 + lrow) * D_MODEL + lseg;

    // ldmatrix per-lane address components
    const int aoff = (lane & 15) * AS2 + (lane >> 4) * 4;                          // A/x4
    const int boff = ((lane & 7) + (lane >> 4) * 8) * AS2 + ((lane >> 3) & 1) * 4; // B-pair/x4

    // prologue: LDG tile 0
    float4 ra[4], rw[4];
    #pragma unroll
    for (int i = 0; i < 4; i++) {
        ra[i] = *(const float4*)(Ap + i * 4);
        rw[i] = *(const float4*)(Wp + i * 4);
    }

    const int NKT = D_MODEL / 32;
    for (int kt = 0; kt < NKT; kt++) {
        // STS tile kt (rounded to tf32) into buf kt&1
        float* Ab = As + (kt & 1) * 128 * AS2;
        float* Wb = Ws + (kt & 1) * 128 * AS2;
        #pragma unroll
        for (int i = 0; i < 4; i++) {
            float4 va = ra[i], vw = rw[i];
            va.x = f2tff(va.x); va.y = f2tff(va.y);
            va.z = f2tff(va.z); va.w = f2tff(va.w);
            vw.x = f2tff(vw.x); vw.y = f2tff(vw.y);
            vw.z = f2tff(vw.z); vw.w = f2tff(vw.w);
            *(float4*)&Ab[lrow * AS2 + lseg + i * 4] = va;
            *(float4*)&Wb[lrow * AS2 + lseg + i * 4] = vw;
        }
        __syncthreads();

        // LDG tile kt+1 (overlaps compute below)
        if (kt + 1 < NKT) {
            const int k0 = (kt + 1) * 32;
            #pragma unroll
            for (int i = 0; i < 4; i++) {
                ra[i] = *(const float4*)(Ap + k0 + i * 4);
                rw[i] = *(const float4*)(Wp + k0 + i * 4);
            }
        }

        // compute: 4 k8 steps, fragments via ldmatrix
        const float* aB = Ab + (wm * 64) * AS2 + aoff;
        const float* bB = Wb + (wn * 32) * AS2 + boff;
        #pragma unroll
        for (int kk = 0; kk < 4; kk++) {
            unsigned a[4][4];
            #pragma unroll
            for (int i = 0; i < 4; i++)
                ldsm4(a[i][0], a[i][1], a[i][2], a[i][3],
                      aB + i * 16 * AS2 + kk * 8);
            unsigned rb[8];
            ldsm4(rb[0], rb[1], rb[2], rb[3], bB + kk * 8);             // j=0,1
            ldsm4(rb[4], rb[5], rb[6], rb[7], bB + 16 * AS2 + kk * 8);  // j=2,3
            #pragma unroll
            for (int j = 0; j < 4; j++) {
                #pragma unroll
                for (int i = 0; i < 4; i++)
                    mma8(c[i][j], a[i], rb[j * 2], rb[j * 2 + 1]);
            }
        }
        // no trailing sync: next iter's STS targets the other buffer, whose
        // last readers were iter kt-1 (separated by this iter's sync).
    }

    // ---- epilogue: direct STG from fragments, bias in registers ----
    #pragma unroll
    for (int j = 0; j < 4; j++) {
        const int col = n0 + wn * 32 + j * 8 + 2 * q4;
        const float2 bb = *(const float2*)&bias[col];
        #pragma unroll
        for (int i = 0; i < 4; i++) {
            const int row = m0 + wm * 64 + i * 16 + g4;
            float2 v0, v1;
            v0.x = (c[i][j][0] + bb.x) * scale;
            v0.y = (c[i][j][1] + bb.y) * scale;
            v1.x = (c[i][j][2] + bb.x) * scale;
            v1.y = (c[i][j][3] + bb.y) * scale;
            if (ROUND) {
                v0.x = f2tff(v0.x); v0.y = f2tff(v0.y);
                v1.x = f2tff(v1.x); v1.y = f2tff(v1.y);
            }
            if (TRANSV) {
                // Vt[b][channel][token]: idx = (b*D_MODEL + col)*SEQ + token
                const int b0i = row >> 11, tl0 = row & 2047;
                const int b1i = (row + 8) >> 11, tl1 = (row + 8) & 2047;
                C[((size_t)b0i * D_MODEL + col)     * SEQ + tl0] = v0.x;
                C[((size_t)b0i * D_MODEL + col + 1) * SEQ + tl0] = v0.y;
                C[((size_t)b1i * D_MODEL + col)     * SEQ + tl1] = v1.x;
                C[((size_t)b1i * D_MODEL + col + 1) * SEQ + tl1] = v1.y;
            } else {
                *(float2*)&C[(size_t)row * D_MODEL + col] = v0;
                *(float2*)&C[(size_t)(row + 8) * D_MODEL + col] = v1;
            }
        }
    }
}

// ---------------------------------------------------------------------------
// Flash attention, mma.sync m16n8k8 tf32, register accumulators.
// Q/K arrive [token][channel] tf32-pre-rounded; V arrives TRANSPOSED
// [b][channel][token] -> PV B-fragments via ldmatrix (same pattern as K).
// ---------------------------------------------------------------------------
#define KS 68
#define VTS 68
#define PS 68
#define NTILES (SEQ / 64)
#define ATTN_SMEM ((128*PS + 2*64*KS + 2*64*VTS) * (int)sizeof(float))  // 104448

__global__ __launch_bounds__(256, 2) void attn_mma(
    const float* __restrict__ Qb, const float* __restrict__ Kb,
    const float* __restrict__ Vt, float* __restrict__ Ob)
{
    extern __shared__ float sm[];
    float* Ps = sm;                         // [128][PS]  (Q staging, then P)
    float* Kbuf = Ps + 128 * PS;            // [2][64][KS]
    float* Vbuf = Kbuf + 2 * 64 * KS;       // [2][64][VTS]  rows = d, cols = token

    const int qt = blockIdx.x, h = blockIdx.y, b = blockIdx.z;
    const int t = threadIdx.x, w = t >> 5, lane = t & 31;
    const int g4 = lane >> 2, q4 = lane & 3;
    const int base_q = b * SEQ + qt * 128;
    const int hcol = h * HEAD_DIM;

    // ldmatrix per-lane address components
    const int koff = ((lane & 7) + (lane >> 4) * 8) * KS + ((lane >> 3) & 1) * 4;   // K-pair
    const int voff = ((lane & 7) + (lane >> 4) * 8) * VTS + ((lane >> 3) & 1) * 4;  // V-pair
    const int poff = (lane & 15) * PS + (lane >> 4) * 4;                             // P/x4

    // V global base for this (b, h): Vt[(b*D_MODEL + hcol + d)*SEQ + token]
    const float* Vbase = Vt + ((size_t)b * D_MODEL + hcol) * SEQ;

    // --- stage tile 0 of K/V via cp.async ---
    {
        #pragma unroll
        for (int i = 0; i < 4; i++) {
            const int id = t + i * 256;
            const int row = id >> 4, seg = (id & 15) * 4;
            cp_async16(&Kbuf[row * KS + seg],
                       Kb + (size_t)(b * SEQ + row) * D_MODEL + hcol + seg);
            cp_async16(&Vbuf[row * VTS + seg],
                       Vbase + (size_t)row * SEQ + seg);
        }
    }
    CP_COMMIT();

    // --- stage Q and load A-fragments (already tf32 bit patterns) ---
    {
        const int r = t >> 1;
        const int c0 = (t & 1) * 32;
        #pragma unroll
        for (int i = 0; i < 8; i++)
            *(float4*)&Ps[r * PS + c0 + i * 4] =
                *(const float4*)&Qb[(size_t)(base_q + r) * D_MODEL + hcol + c0 + i * 4];
    }
    __syncwarp();

    unsigned qa[8][4];
    {
        const float* qB = Ps + (w * 16) * PS + poff;
        #pragma unroll
        for (int kk = 0; kk < 8; kk++)
            ldsm4(qa[kk][0], qa[kk][1], qa[kk][2], qa[kk][3], qB + kk * 8);
    }
    __syncwarp();   // Ps free for P reuse

    float of[8][4];
    #pragma unroll
    for (int n = 0; n < 8; n++)
        of[n][0] = of[n][1] = of[n][2] = of[n][3] = 0.f;
    float m0r = -1e30f, m1r = -1e30f, l0r = 0.f, l1r = 0.f;

    for (int jt = 0; jt < NTILES; jt++) {
        float* Kc = Kbuf + (jt & 1) * 64 * KS;
        float* Vc = Vbuf + (jt & 1) * 64 * VTS;

        if (jt + 1 < NTILES) {
            float* Kn = Kbuf + ((jt + 1) & 1) * 64 * KS;
            float* Vn = Vbuf + ((jt + 1) & 1) * 64 * VTS;
            const int tok0 = (jt + 1) * 64;
            #pragma unroll
            for (int i = 0; i < 4; i++) {
                const int id = t + i * 256;
                const int row = id >> 4, seg = (id & 15) * 4;
                cp_async16(&Kn[row * KS + seg],
                           Kb + (size_t)(b * SEQ + tok0 + row) * D_MODEL + hcol + seg);
                cp_async16(&Vn[row * VTS + seg],
                           Vbase + (size_t)row * SEQ + tok0 + seg);
            }
        }
        CP_COMMIT();
        CP_WAIT1();          // tile jt resident; jt+1 in flight
        __syncthreads();

        // ---- S = Q @ K^T  (K fragments via ldmatrix, 2 n-blocks per op) ----
        float sfr[8][4];
        #pragma unroll
        for (int n = 0; n < 8; n++)
            sfr[n][0] = sfr[n][1] = sfr[n][2] = sfr[n][3] = 0.f;
        {
            const float* kB = Kc + koff;
            #pragma unroll
            for (int kk = 0; kk < 8; kk++) {
                #pragma unroll
                for (int jp = 0; jp < 4; jp++) {
                    unsigned rb[4];
                    ldsm4(rb[0], rb[1], rb[2], rb[3], kB + jp * 16 * KS + kk * 8);
                    mma8(sfr[jp * 2],     qa[kk], rb[0], rb[1]);
                    mma8(sfr[jp * 2 + 1], qa[kk], rb[2], rb[3]);
                }
            }
        }

        // ---- online softmax in registers ----
        float mx0 = -1e30f, mx1 = -1e30f;
        #pragma unroll
        for (int n = 0; n < 8; n++) {
            mx0 = fmaxf(mx0, fmaxf(sfr[n][0], sfr[n][1]));
            mx1 = fmaxf(mx1, fmaxf(sfr[n][2], sfr[n][3]));
        }
        mx0 = fmaxf(mx0, __shfl_xor_sync(0xffffffffu, mx0, 1));
        mx0 = fmaxf(mx0, __shfl_xor_sync(0xffffffffu, mx0, 2));
        mx1 = fmaxf(mx1, __shfl_xor_sync(0xffffffffu, mx1, 1));
        mx1 = fmaxf(mx1, __shfl_xor_sync(0xffffffffu, mx1, 2));

        const float mn0 = fmaxf(m0r, mx0);
        const float mn1 = fmaxf(m1r, mx1);
        const float a0 = __expf(m0r - mn0);
        const float a1 = __expf(m1r - mn1);
        m0r = mn0; m1r = mn1;

        float s0 = 0.f, s1 = 0.f;
        #pragma unroll
        for (int n = 0; n < 8; n++) {
            sfr[n][0] = __expf(sfr[n][0] - mn0);
            sfr[n][1] = __expf(sfr[n][1] - mn0);
            sfr[n][2] = __expf(sfr[n][2] - mn1);
            sfr[n][3] = __expf(sfr[n][3] - mn1);
            s0 += sfr[n][0] + sfr[n][1];
            s1 += sfr[n][2] + sfr[n][3];
            of[n][0] *= a0; of[n][1] *= a0;
            of[n][2] *= a1; of[n][3] *= a1;
            *(float2*)&Ps[(w * 16 + g4)     * PS + n * 8 + 2 * q4] =
                make_float2(sfr[n][0], sfr[n][1]);
            *(float2*)&Ps[(w * 16 + g4 + 8) * PS + n * 8 + 2 * q4] =
                make_float2(sfr[n][2], sfr[n][3]);
        }
        s0 += __shfl_xor_sync(0xffffffffu, s0, 1);
        s0 += __shfl_xor_sync(0xffffffffu, s0, 2);
        s1 += __shfl_xor_sync(0xffffffffu, s1, 1);
        s1 += __shfl_xor_sync(0xffffffffu, s1, 2);
        l0r = l0r * a0 + s0;
        l1r = l1r * a1 + s1;
        __syncwarp();

        // ---- O += P @ V  (P via ldmatrix + cvt; V via ldmatrix on Vt) ----
        {
            const float* pB = Ps + (w * 16) * PS + poff;
            const float* vB = Vc + voff;
            #pragma unroll
            for (int kk = 0; kk < 8; kk++) {
                unsigned r0, r1, r2, r3;
                ldsm4(r0, r1, r2, r3, pB + kk * 8);
                unsigned pa[4];
                pa[0] = cvtu(r0); pa[1] = cvtu(r1);
                pa[2] = cvtu(r2); pa[3] = cvtu(r3);
                #pragma unroll
                for (int jp = 0; jp < 4; jp++) {
                    unsigned rb[4];
                    ldsm4(rb[0], rb[1], rb[2], rb[3], vB + jp * 16 * VTS + kk * 8);
                    mma8(of[jp * 2],     pa, rb[0], rb[1]);
                    mma8(of[jp * 2 + 1], pa, rb[2], rb[3]);
                }
            }
        }
        __syncwarp();
        __syncthreads();   // all warps done with Kc/Vc before restaging
    }

    // ---- epilogue: normalize, write [B,T,H*hd] ----
    const float inv0 = 1.f / l0r;
    const float inv1 = 1.f / l1r;
    const int r0 = base_q + w * 16 + g4;
    #pragma unroll
    for (int n = 0; n < 8; n++) {
        const int c = hcol + n * 8 + 2 * q4;
        *(float2*)&Ob[(size_t)r0 * D_MODEL + c] =
            make_float2(of[n][0] * inv0, of[n][1] * inv0);
        *(float2*)&Ob[(size_t)(r0 + 8) * D_MODEL + c] =
            make_float2(of[n][2] * inv1, of[n][3] * inv1);
    }
}

// ---------------------------------------------------------------------------
extern "C" void kernel_launch(void* const* d_in, const int* in_sizes, int n_in,
                              void* d_out, int out_size)
{
    const float* query = (const float*)d_in[0];
    const float* key   = (const float*)d_in[1];
    const float* value = (const float*)d_in[2];
    const float* Wq    = (const float*)d_in[3];
    const float* bq    = (const float*)d_in[4];
    const float* Wk    = (const float*)d_in[5];
    const float* bk    = (const float*)d_in[6];
    const float* Wv    = (const float*)d_in[7];
    const float* bv    = (const float*)d_in[8];
    const float* Wo    = (const float*)d_in[9];
    const float* bo    = (const float*)d_in[10];
    float* out = (float*)d_out;

    float *pQ, *pK, *pVt, *pA;
    cudaGetSymbolAddress((void**)&pQ, g_Q);
    cudaGetSymbolAddress((void**)&pK, g_K);
    cudaGetSymbolAddress((void**)&pVt, g_Vt);
    cudaGetSymbolAddress((void**)&pA, g_Attn);

    cudaFuncSetAttribute((const void*)gemm_mma<true, false>,
                         cudaFuncAttributeMaxDynamicSharedMemorySize, GEMM_SMEM);
    cudaFuncSetAttribute((const void*)gemm_mma<true, true>,
                         cudaFuncAttributeMaxDynamicSharedMemorySize, GEMM_SMEM);
    cudaFuncSetAttribute((const void*)gemm_mma<false, false>,
                         cudaFuncAttributeMaxDynamicSharedMemorySize, GEMM_SMEM);
    cudaFuncSetAttribute((const void*)attn_mma,
                         cudaFuncAttributeMaxDynamicSharedMemorySize, ATTN_SMEM);

    dim3 gemm_grid(D_MODEL / 128, MTOT / 128);   // (8, 32)
    const float qscale = 0.125f;                 // 1/sqrt(64)

    gemm_mma<true, false><<<gemm_grid, 256, GEMM_SMEM>>>(query, Wq, bq, qscale, pQ);
    gemm_mma<true, false><<<gemm_grid, 256, GEMM_SMEM>>>(key,   Wk, bk, 1.f,    pK);
    gemm_mma<true, true ><<<gemm_grid, 256, GEMM_SMEM>>>(value, Wv, bv, 1.f,    pVt);

    dim3 attn_grid(SEQ / 128, NHEAD, BATCH);     // (16, 16, 2)
    attn_mma<<<attn_grid, 256, ATTN_SMEM>>>(pQ, pK, pVt, pA);

    gemm_mma<false, false><<<gemm_grid, 256, GEMM_SMEM>>>(pA, Wo, bo, 1.f, out);
}

// round 13
// speedup vs baseline: 1.4147x; 1.2634x over previous
#include <cuda_runtime.h>
#include <cuda_fp16.h>
#include <cstdint>
#include <math.h>

#define D_MODEL 1024
#define NHEAD 16
#define HEAD_DIM 64
#define BATCH 2
#define SEQ 2048
#define MTOT (BATCH*SEQ)   // 4096

// Scratch (allocation-free rule: __device__ globals)
__device__ __half g_Q[MTOT * D_MODEL];
__device__ __half g_K[MTOT * D_MODEL];
__device__ __half g_Vt[MTOT * D_MODEL];  // V projection, TRANSPOSED: [b][channel][token]
__device__ float  g_Attn[MTOT * D_MODEL];

// ---------------------------------------------------------------------------
// helpers
// ---------------------------------------------------------------------------
__device__ __forceinline__ unsigned f2tf(float x) {
    unsigned u;
    asm("cvt.rna.tf32.f32 %0, %1;" : "=r"(u) : "f"(x));
    return u;
}
__device__ __forceinline__ float f2tff(float x) { return __uint_as_float(f2tf(x)); }

// tf32 mma (GEMM path)
__device__ __forceinline__ void mma8(float* c, const unsigned* a,
                                     unsigned b0, unsigned b1) {
    asm volatile(
        "mma.sync.aligned.m16n8k8.row.col.f32.tf32.tf32.f32 "
        "{%0,%1,%2,%3}, {%4,%5,%6,%7}, {%8,%9}, {%0,%1,%2,%3};"
        : "+f"(c[0]), "+f"(c[1]), "+f"(c[2]), "+f"(c[3])
        : "r"(a[0]), "r"(a[1]), "r"(a[2]), "r"(a[3]), "r"(b0), "r"(b1));
}

// fp16 mma (attention path)
__device__ __forceinline__ void mma16h(float* c, const unsigned* a,
                                       unsigned b0, unsigned b1) {
    asm volatile(
        "mma.sync.aligned.m16n8k16.row.col.f32.f16.f16.f32 "
        "{%0,%1,%2,%3}, {%4,%5,%6,%7}, {%8,%9}, {%0,%1,%2,%3};"
        : "+f"(c[0]), "+f"(c[1]), "+f"(c[2]), "+f"(c[3])
        : "r"(a[0]), "r"(a[1]), "r"(a[2]), "r"(a[3]), "r"(b0), "r"(b1));
}

__device__ __forceinline__ void ldsm4(unsigned& r0, unsigned& r1,
                                      unsigned& r2, unsigned& r3, const void* p) {
    unsigned addr = (unsigned)__cvta_generic_to_shared(p);
    asm volatile("ldmatrix.sync.aligned.m8n8.x4.shared.b16 {%0,%1,%2,%3}, [%4];"
        : "=r"(r0), "=r"(r1), "=r"(r2), "=r"(r3) : "r"(addr));
}

__device__ __forceinline__ void cp_async16(void* dst, const void* src) {
    unsigned int d = (unsigned int)__cvta_generic_to_shared(dst);
    asm volatile("cp.async.cg.shared.global [%0], [%1], 16;" :: "r"(d), "l"(src));
}
#define CP_COMMIT() asm volatile("cp.async.commit_group;")
#define CP_WAIT1()  asm volatile("cp.async.wait_group 1;")

// ---------------------------------------------------------------------------
// Hand-rolled tf32 GEMM (R11-proven):  C = (A @ W^T + bias) * scale
// OM (out mode): 0 = f32 [token][channel] (final Wo output)
//                1 = half [token][channel] (Q, K)
//                2 = half TRANSPOSED [b][channel][token] (Vt)
// 128x128 block, BK=32, 8 warps (2x4), warp tile 64x32, mma.m16n8k8.
// Operands tf32-rounded at staging; inner loop = LDSM + HMMA only.
// smem stride 36 -> every ldmatrix phase conflict-free.
// ---------------------------------------------------------------------------
#define AS2 36
#define GEMM_SMEM (4 * 128 * AS2 * (int)sizeof(float))   // 73728 bytes

template<int OM>
__global__ __launch_bounds__(256, 2) void gemm_mma(
    const float* __restrict__ A, const float* __restrict__ W,
    const float* __restrict__ bias, float scale, void* __restrict__ Cv)
{
    extern __shared__ float sm[];
    float* As = sm;                   // [2][128*AS2]
    float* Ws = sm + 2 * 128 * AS2;   // [2][128*AS2]

    const int m0 = blockIdx.y * 128;
    const int n0 = blockIdx.x * 128;
    const int t  = threadIdx.x;
    const int wid = t >> 5, lane = t & 31;
    const int g4 = lane >> 2, q4 = lane & 3;
    const int wm = wid >> 2;          // 0..1
    const int wn = wid & 3;           // 0..3
    const int lrow = t >> 1;          // 0..127
    const int lseg = (t & 1) * 16;

    float c[4][4][4];
    #pragma unroll
    for (int i = 0; i < 4; i++)
        #pragma unroll
        for (int j = 0; j < 4; j++)
            c[i][j][0] = c[i][j][1] = c[i][j][2] = c[i][j][3] = 0.f;

    const float* Ap = A + (size_t)(m0 + lrow) * D_MODEL + lseg;
    const float* Wp = W + (size_t)(n0 + lrow) * D_MODEL + lseg;

    const int aoff = (lane & 15) * AS2 + (lane >> 4) * 4;
    const int boff = ((lane & 7) + (lane >> 4) * 8) * AS2 + ((lane >> 3) & 1) * 4;

    float4 ra[4], rw[4];
    #pragma unroll
    for (int i = 0; i < 4; i++) {
        ra[i] = *(const float4*)(Ap + i * 4);
        rw[i] = *(const float4*)(Wp + i * 4);
    }

    const int NKT = D_MODEL / 32;
    for (int kt = 0; kt < NKT; kt++) {
        float* Ab = As + (kt & 1) * 128 * AS2;
        float* Wb = Ws + (kt & 1) * 128 * AS2;
        #pragma unroll
        for (int i = 0; i < 4; i++) {
            float4 va = ra[i], vw = rw[i];
            va.x = f2tff(va.x); va.y = f2tff(va.y);
            va.z = f2tff(va.z); va.w = f2tff(va.w);
            vw.x = f2tff(vw.x); vw.y = f2tff(vw.y);
            vw.z = f2tff(vw.z); vw.w = f2tff(vw.w);
            *(float4*)&Ab[lrow * AS2 + lseg + i * 4] = va;
            *(float4*)&Wb[lrow * AS2 + lseg + i * 4] = vw;
        }
        __syncthreads();

        if (kt + 1 < NKT) {
            const int k0 = (kt + 1) * 32;
            #pragma unroll
            for (int i = 0; i < 4; i++) {
                ra[i] = *(const float4*)(Ap + k0 + i * 4);
                rw[i] = *(const float4*)(Wp + k0 + i * 4);
            }
        }

        const float* aB = Ab + (wm * 64) * AS2 + aoff;
        const float* bB = Wb + (wn * 32) * AS2 + boff;
        #pragma unroll
        for (int kk = 0; kk < 4; kk++) {
            unsigned a[4][4];
            #pragma unroll
            for (int i = 0; i < 4; i++)
                ldsm4(a[i][0], a[i][1], a[i][2], a[i][3],
                      aB + i * 16 * AS2 + kk * 8);
            unsigned rb[8];
            ldsm4(rb[0], rb[1], rb[2], rb[3], bB + kk * 8);
            ldsm4(rb[4], rb[5], rb[6], rb[7], bB + 16 * AS2 + kk * 8);
            #pragma unroll
            for (int j = 0; j < 4; j++) {
                #pragma unroll
                for (int i = 0; i < 4; i++)
                    mma8(c[i][j], a[i], rb[j * 2], rb[j * 2 + 1]);
            }
        }
    }

    // ---- epilogue: direct STG from fragments, bias in registers ----
    #pragma unroll
    for (int j = 0; j < 4; j++) {
        const int col = n0 + wn * 32 + j * 8 + 2 * q4;
        const float2 bb = *(const float2*)&bias[col];
        #pragma unroll
        for (int i = 0; i < 4; i++) {
            const int row = m0 + wm * 64 + i * 16 + g4;
            float2 v0, v1;
            v0.x = (c[i][j][0] + bb.x) * scale;
            v0.y = (c[i][j][1] + bb.y) * scale;
            v1.x = (c[i][j][2] + bb.x) * scale;
            v1.y = (c[i][j][3] + bb.y) * scale;
            if (OM == 0) {
                float* C = (float*)Cv;
                *(float2*)&C[(size_t)row * D_MODEL + col] = v0;
                *(float2*)&C[(size_t)(row + 8) * D_MODEL + col] = v1;
            } else if (OM == 1) {
                __half* C = (__half*)Cv;
                *(__half2*)(C + (size_t)row * D_MODEL + col) =
                    __floats2half2_rn(v0.x, v0.y);
                *(__half2*)(C + (size_t)(row + 8) * D_MODEL + col) =
                    __floats2half2_rn(v1.x, v1.y);
            } else {
                __half* C = (__half*)Cv;
                const int b0i = row >> 11, tl0 = row & 2047;
                const int b1i = (row + 8) >> 11, tl1 = (row + 8) & 2047;
                C[((size_t)b0i * D_MODEL + col)     * SEQ + tl0] = __float2half_rn(v0.x);
                C[((size_t)b0i * D_MODEL + col + 1) * SEQ + tl0] = __float2half_rn(v0.y);
                C[((size_t)b1i * D_MODEL + col)     * SEQ + tl1] = __float2half_rn(v1.x);
                C[((size_t)b1i * D_MODEL + col + 1) * SEQ + tl1] = __float2half_rn(v1.y);
            }
        }
    }
}

// ---------------------------------------------------------------------------
// Flash attention, fp16 mma.m16n8k16, fp32 accumulators/softmax.
// Q/K half [token][channel]; V half TRANSPOSED [b][channel][token].
// All fragments via ldmatrix.b16 (native); P stashed as half2.
// Strides in HALF units; HS=72 halves = 144B -> 4-bank row step, conflict-free.
// ---------------------------------------------------------------------------
#define HS 72
#define NTILES (SEQ / 64)
// halves: Ps 128*72 + K 2*64*72 + V 2*64*72 = 27648 -> 55296 bytes
#define ATTN_SMEM ((128*HS + 2*64*HS + 2*64*HS) * (int)sizeof(__half))

__global__ __launch_bounds__(256, 2) void attn_h(
    const __half* __restrict__ Qb, const __half* __restrict__ Kb,
    const __half* __restrict__ Vt, float* __restrict__ Ob)
{
    extern __shared__ __half smh[];
    __half* Ps   = smh;                      // [128][HS]  (Q staging, then P)
    __half* Kbuf = Ps + 128 * HS;            // [2][64][HS]
    __half* Vbuf = Kbuf + 2 * 64 * HS;       // [2][64][HS]  rows = d, cols = token

    const int qt = blockIdx.x, h = blockIdx.y, b = blockIdx.z;
    const int t = threadIdx.x, w = t >> 5, lane = t & 31;
    const int g4 = lane >> 2, q4 = lane & 3;
    const int base_q = b * SEQ + qt * 128;
    const int hcol = h * HEAD_DIM;

    // ldmatrix per-lane offsets (HALF units)
    const int koff = ((lane & 7) + ((lane >> 4) << 3)) * HS + ((lane >> 3) & 1) * 8;
    const int poff = (lane & 15) * HS + (lane >> 4) * 8;

    const __half* Vbase = Vt + ((size_t)b * D_MODEL + hcol) * SEQ;

    // --- stage tile 0 of K/V via cp.async (16B = 8 halves per op) ---
    {
        #pragma unroll
        for (int i = 0; i < 2; i++) {
            const int cid = t + i * 256;            // 0..511
            const int row = cid >> 3, seg = (cid & 7) * 8;
            cp_async16(&Kbuf[row * HS + seg],
                       Kb + (size_t)(b * SEQ + row) * D_MODEL + hcol + seg);
            cp_async16(&Vbuf[row * HS + seg],
                       Vbase + (size_t)row * SEQ + seg);
        }
    }
    CP_COMMIT();

    // --- stage Q (half) and load A-fragments ---
    {
        const int r = t >> 1;
        const int c0 = (t & 1) * 32;                // halves
        #pragma unroll
        for (int i = 0; i < 4; i++)
            *(float4*)&Ps[r * HS + c0 + i * 8] =
                *(const float4*)(Qb + (size_t)(base_q + r) * D_MODEL + hcol + c0 + i * 8);
    }
    __syncwarp();

    unsigned qa[4][4];
    {
        const __half* qB = Ps + (w * 16) * HS + poff;
        #pragma unroll
        for (int kk = 0; kk < 4; kk++)
            ldsm4(qa[kk][0], qa[kk][1], qa[kk][2], qa[kk][3], qB + kk * 16);
    }
    __syncwarp();   // Ps free for P reuse

    float of[8][4];
    #pragma unroll
    for (int n = 0; n < 8; n++)
        of[n][0] = of[n][1] = of[n][2] = of[n][3] = 0.f;
    float m0r = -1e30f, m1r = -1e30f, l0r = 0.f, l1r = 0.f;

    for (int jt = 0; jt < NTILES; jt++) {
        __half* Kc = Kbuf + (jt & 1) * 64 * HS;
        __half* Vc = Vbuf + (jt & 1) * 64 * HS;

        if (jt + 1 < NTILES) {
            __half* Kn = Kbuf + ((jt + 1) & 1) * 64 * HS;
            __half* Vn = Vbuf + ((jt + 1) & 1) * 64 * HS;
            const int tok0 = (jt + 1) * 64;
            #pragma unroll
            for (int i = 0; i < 2; i++) {
                const int cid = t + i * 256;
                const int row = cid >> 3, seg = (cid & 7) * 8;
                cp_async16(&Kn[row * HS + seg],
                           Kb + (size_t)(b * SEQ + tok0 + row) * D_MODEL + hcol + seg);
                cp_async16(&Vn[row * HS + seg],
                           Vbase + (size_t)row * SEQ + tok0 + seg);
            }
        }
        CP_COMMIT();
        CP_WAIT1();          // tile jt resident; jt+1 in flight
        __syncthreads();

        // ---- S = Q @ K^T : 4 k16-steps, 8 n-blocks (2 per ldsm.x4) ----
        float sfr[8][4];
        #pragma unroll
        for (int n = 0; n < 8; n++)
            sfr[n][0] = sfr[n][1] = sfr[n][2] = sfr[n][3] = 0.f;
        {
            const __half* kB = Kc + koff;
            #pragma unroll
            for (int kk = 0; kk < 4; kk++) {
                #pragma unroll
                for (int jp = 0; jp < 4; jp++) {
                    unsigned rb[4];
                    ldsm4(rb[0], rb[1], rb[2], rb[3], kB + jp * 16 * HS + kk * 16);
                    mma16h(sfr[jp * 2],     qa[kk], rb[0], rb[1]);
                    mma16h(sfr[jp * 2 + 1], qa[kk], rb[2], rb[3]);
                }
            }
        }

        // ---- online softmax in registers (fp32) ----
        float mx0 = -1e30f, mx1 = -1e30f;
        #pragma unroll
        for (int n = 0; n < 8; n++) {
            mx0 = fmaxf(mx0, fmaxf(sfr[n][0], sfr[n][1]));
            mx1 = fmaxf(mx1, fmaxf(sfr[n][2], sfr[n][3]));
        }
        mx0 = fmaxf(mx0, __shfl_xor_sync(0xffffffffu, mx0, 1));
        mx0 = fmaxf(mx0, __shfl_xor_sync(0xffffffffu, mx0, 2));
        mx1 = fmaxf(mx1, __shfl_xor_sync(0xffffffffu, mx1, 1));
        mx1 = fmaxf(mx1, __shfl_xor_sync(0xffffffffu, mx1, 2));

        const float mn0 = fmaxf(m0r, mx0);
        const float mn1 = fmaxf(m1r, mx1);
        const float a0 = __expf(m0r - mn0);
        const float a1 = __expf(m1r - mn1);
        m0r = mn0; m1r = mn1;

        float s0 = 0.f, s1 = 0.f;
        #pragma unroll
        for (int n = 0; n < 8; n++) {
            sfr[n][0] = __expf(sfr[n][0] - mn0);
            sfr[n][1] = __expf(sfr[n][1] - mn0);
            sfr[n][2] = __expf(sfr[n][2] - mn1);
            sfr[n][3] = __expf(sfr[n][3] - mn1);
            s0 += sfr[n][0] + sfr[n][1];
            s1 += sfr[n][2] + sfr[n][3];
            of[n][0] *= a0; of[n][1] *= a0;
            of[n][2] *= a1; of[n][3] *= a1;
            // stash P as half2 (warp-private strip)
            *(__half2*)&Ps[(w * 16 + g4)     * HS + n * 8 + 2 * q4] =
                __floats2half2_rn(sfr[n][0], sfr[n][1]);
            *(__half2*)&Ps[(w * 16 + g4 + 8) * HS + n * 8 + 2 * q4] =
                __floats2half2_rn(sfr[n][2], sfr[n][3]);
        }
        s0 += __shfl_xor_sync(0xffffffffu, s0, 1);
        s0 += __shfl_xor_sync(0xffffffffu, s0, 2);
        s1 += __shfl_xor_sync(0xffffffffu, s1, 1);
        s1 += __shfl_xor_sync(0xffffffffu, s1, 2);
        l0r = l0r * a0 + s0;
        l1r = l1r * a1 + s1;
        __syncwarp();

        // ---- O += P @ V : 4 k16-steps; P and V fragments via ldmatrix ----
        {
            const __half* pB = Ps + (w * 16) * HS + poff;
            const __half* vB = Vc + koff;   // Vt rows = d, cols = token
            #pragma unroll
            for (int kk = 0; kk < 4; kk++) {
                unsigned pa[4];
                ldsm4(pa[0], pa[1], pa[2], pa[3], pB + kk * 16);
                #pragma unroll
                for (int jp = 0; jp < 4; jp++) {
                    unsigned rb[4];
                    ldsm4(rb[0], rb[1], rb[2], rb[3], vB + jp * 16 * HS + kk * 16);
                    mma16h(of[jp * 2],     pa, rb[0], rb[1]);
                    mma16h(of[jp * 2 + 1], pa, rb[2], rb[3]);
                }
            }
        }
        __syncwarp();
        __syncthreads();   // all warps done with Kc/Vc before restaging
    }

    // ---- epilogue: normalize, write f32 [B,T,H*hd] ----
    const float inv0 = 1.f / l0r;
    const float inv1 = 1.f / l1r;
    const int r0 = base_q + w * 16 + g4;
    #pragma unroll
    for (int n = 0; n < 8; n++) {
        const int c = hcol + n * 8 + 2 * q4;
        *(float2*)&Ob[(size_t)r0 * D_MODEL + c] =
            make_float2(of[n][0] * inv0, of[n][1] * inv0);
        *(float2*)&Ob[(size_t)(r0 + 8) * D_MODEL + c] =
            make_float2(of[n][2] * inv1, of[n][3] * inv1);
    }
}

// ---------------------------------------------------------------------------
extern "C" void kernel_launch(void* const* d_in, const int* in_sizes, int n_in,
                              void* d_out, int out_size)
{
    const float* query = (const float*)d_in[0];
    const float* key   = (const float*)d_in[1];
    const float* value = (const float*)d_in[2];
    const float* Wq    = (const float*)d_in[3];
    const float* bq    = (const float*)d_in[4];
    const float* Wk    = (const float*)d_in[5];
    const float* bk    = (const float*)d_in[6];
    const float* Wv    = (const float*)d_in[7];
    const float* bv    = (const float*)d_in[8];
    const float* Wo    = (const float*)d_in[9];
    const float* bo    = (const float*)d_in[10];
    float* out = (float*)d_out;

    __half *pQ, *pK, *pVt;
    float *pA;
    cudaGetSymbolAddress((void**)&pQ, g_Q);
    cudaGetSymbolAddress((void**)&pK, g_K);
    cudaGetSymbolAddress((void**)&pVt, g_Vt);
    cudaGetSymbolAddress((void**)&pA, g_Attn);

    cudaFuncSetAttribute((const void*)gemm_mma<0>,
                         cudaFuncAttributeMaxDynamicSharedMemorySize, GEMM_SMEM);
    cudaFuncSetAttribute((const void*)gemm_mma<1>,
                         cudaFuncAttributeMaxDynamicSharedMemorySize, GEMM_SMEM);
    cudaFuncSetAttribute((const void*)gemm_mma<2>,
                         cudaFuncAttributeMaxDynamicSharedMemorySize, GEMM_SMEM);
    cudaFuncSetAttribute((const void*)attn_h,
                         cudaFuncAttributeMaxDynamicSharedMemorySize, ATTN_SMEM);

    dim3 gemm_grid(D_MODEL / 128, MTOT / 128);   // (8, 32)
    const float qscale = 0.125f;                 // 1/sqrt(64)

    gemm_mma<1><<<gemm_grid, 256, GEMM_SMEM>>>(query, Wq, bq, qscale, pQ);
    gemm_mma<1><<<gemm_grid, 256, GEMM_SMEM>>>(key,   Wk, bk, 1.f,    pK);
    gemm_mma<2><<<gemm_grid, 256, GEMM_SMEM>>>(value, Wv, bv, 1.f,    pVt);

    dim3 attn_grid(SEQ / 128, NHEAD, BATCH);     // (16, 16, 2)
    attn_h<<<attn_grid, 256, ATTN_SMEM>>>(pQ, pK, pVt, pA);

    gemm_mma<0><<<gemm_grid, 256, GEMM_SMEM>>>(pA, Wo, bo, 1.f, out);
}

// round 14
// speedup vs baseline: 1.7181x; 1.2145x over previous
#include <cuda_runtime.h>
#include <cuda_fp16.h>
#include <cstdint>
#include <math.h>

#define D_MODEL 1024
#define NHEAD 16
#define HEAD_DIM 64
#define BATCH 2
#define SEQ 2048
#define MTOT (BATCH*SEQ)   // 4096

// Scratch (allocation-free rule: __device__ globals)
__device__ __half g_Q[MTOT * D_MODEL];
__device__ __half g_K[MTOT * D_MODEL];
__device__ __half g_Vt[MTOT * D_MODEL];  // V projection, TRANSPOSED: [b][channel][token]
__device__ __half g_Attn[MTOT * D_MODEL];

// ---------------------------------------------------------------------------
// helpers
// ---------------------------------------------------------------------------
// fp16 mma, fp32 accum
__device__ __forceinline__ void mma16h(float* c, const unsigned* a,
                                       unsigned b0, unsigned b1) {
    asm volatile(
        "mma.sync.aligned.m16n8k16.row.col.f32.f16.f16.f32 "
        "{%0,%1,%2,%3}, {%4,%5,%6,%7}, {%8,%9}, {%0,%1,%2,%3};"
        : "+f"(c[0]), "+f"(c[1]), "+f"(c[2]), "+f"(c[3])
        : "r"(a[0]), "r"(a[1]), "r"(a[2]), "r"(a[3]), "r"(b0), "r"(b1));
}

__device__ __forceinline__ void ldsm4(unsigned& r0, unsigned& r1,
                                      unsigned& r2, unsigned& r3, const void* p) {
    unsigned addr = (unsigned)__cvta_generic_to_shared(p);
    asm volatile("ldmatrix.sync.aligned.m8n8.x4.shared.b16 {%0,%1,%2,%3}, [%4];"
        : "=r"(r0), "=r"(r1), "=r"(r2), "=r"(r3) : "r"(addr));
}

__device__ __forceinline__ void cp_async16(void* dst, const void* src) {
    unsigned int d = (unsigned int)__cvta_generic_to_shared(dst);
    asm volatile("cp.async.cg.shared.global [%0], [%1], 16;" :: "r"(d), "l"(src));
}
#define CP_COMMIT() asm volatile("cp.async.commit_group;")
#define CP_WAIT1()  asm volatile("cp.async.wait_group 1;")

// ---------------------------------------------------------------------------
// fp16 GEMM:  C = (A @ W^T + bias) * scale   (fp32 accumulators)
// AT: A element type (float -> converted at staging; __half -> native).
// OM: 0 = f32 [token][channel] (final Wo output)
//     1 = half [token][channel] (Q, K)
//     2 = half TRANSPOSED [b][channel][token] (Vt)
// 128x128 block, BK=32, 8 warps (2x4), warp tile 64x32, mma.m16n8k16.
// smem stride 40 halves (80B): ldmatrix phases cover all 32 banks once.
// ---------------------------------------------------------------------------
#define HS2 40
#define GEMMH_SMEM (4 * 128 * HS2 * (int)sizeof(__half))   // 40960 bytes

template<typename AT, int OM>
__global__ __launch_bounds__(256, 2) void gemm_h(
    const AT* __restrict__ A, const float* __restrict__ W,
    const float* __restrict__ bias, float scale, void* __restrict__ Cv)
{
    extern __shared__ __half smh[];
    __half* As = smh;                   // [2][128*HS2]
    __half* Ws = smh + 2 * 128 * HS2;   // [2][128*HS2]

    const int m0 = blockIdx.y * 128;
    const int n0 = blockIdx.x * 128;
    const int t  = threadIdx.x;
    const int wid = t >> 5, lane = t & 31;
    const int g4 = lane >> 2, q4 = lane & 3;
    const int wm = wid >> 2;          // 0..1
    const int wn = wid & 3;           // 0..3
    const int lrow = t >> 1;          // 0..127
    const int lseg = (t & 1) * 16;    // half-col within 32-wide row

    float c[4][4][4];
    #pragma unroll
    for (int i = 0; i < 4; i++)
        #pragma unroll
        for (int j = 0; j < 4; j++)
            c[i][j][0] = c[i][j][1] = c[i][j][2] = c[i][j][3] = 0.f;

    const AT*    Ap = A + (size_t)(m0 + lrow) * D_MODEL + lseg;
    const float* Wp = W + (size_t)(n0 + lrow) * D_MODEL + lseg;

    // ldmatrix per-lane offsets (half units)
    const int aoff = (lane & 15) * HS2 + (lane >> 4) * 8;
    const int boff = ((lane & 7) + ((lane >> 4) << 3)) * HS2 + ((lane >> 3) & 1) * 8;

    // prologue: LDG tile 0
    float4 ra[4], rw[4];   // for half A only ra[0..1] used
    #pragma unroll
    for (int i = 0; i < 4; i++) rw[i] = *(const float4*)(Wp + i * 4);
    if (sizeof(AT) == 4) {
        #pragma unroll
        for (int i = 0; i < 4; i++) ra[i] = *(const float4*)((const float*)Ap + i * 4);
    } else {
        #pragma unroll
        for (int i = 0; i < 2; i++) ra[i] = *(const float4*)((const __half*)Ap + i * 8);
    }

    const int NKT = D_MODEL / 32;
    for (int kt = 0; kt < NKT; kt++) {
        // STS tile kt (converted to half) into buf kt&1
        __half* Ab = As + (kt & 1) * 128 * HS2;
        __half* Wb = Ws + (kt & 1) * 128 * HS2;
        {
            __half2 hw[8];
            #pragma unroll
            for (int i = 0; i < 4; i++) {
                hw[2*i]   = __floats2half2_rn(rw[i].x, rw[i].y);
                hw[2*i+1] = __floats2half2_rn(rw[i].z, rw[i].w);
            }
            *(float4*)&Wb[lrow * HS2 + lseg]     = *(float4*)&hw[0];
            *(float4*)&Wb[lrow * HS2 + lseg + 8] = *(float4*)&hw[4];
            if (sizeof(AT) == 4) {
                __half2 ha[8];
                #pragma unroll
                for (int i = 0; i < 4; i++) {
                    ha[2*i]   = __floats2half2_rn(ra[i].x, ra[i].y);
                    ha[2*i+1] = __floats2half2_rn(ra[i].z, ra[i].w);
                }
                *(float4*)&Ab[lrow * HS2 + lseg]     = *(float4*)&ha[0];
                *(float4*)&Ab[lrow * HS2 + lseg + 8] = *(float4*)&ha[4];
            } else {
                *(float4*)&Ab[lrow * HS2 + lseg]     = ra[0];
                *(float4*)&Ab[lrow * HS2 + lseg + 8] = ra[1];
            }
        }
        __syncthreads();

        // LDG tile kt+1 (overlaps compute below)
        if (kt + 1 < NKT) {
            const int k0 = (kt + 1) * 32;
            #pragma unroll
            for (int i = 0; i < 4; i++) rw[i] = *(const float4*)(Wp + k0 + i * 4);
            if (sizeof(AT) == 4) {
                #pragma unroll
                for (int i = 0; i < 4; i++)
                    ra[i] = *(const float4*)((const float*)Ap + k0 + i * 4);
            } else {
                #pragma unroll
                for (int i = 0; i < 2; i++)
                    ra[i] = *(const float4*)((const __half*)Ap + k0 + i * 8);
            }
        }

        // compute: 2 k16 steps, fragments via ldmatrix (no cvt needed)
        const __half* aB = Ab + (wm * 64) * HS2 + aoff;
        const __half* bB = Wb + (wn * 32) * HS2 + boff;
        #pragma unroll
        for (int kk = 0; kk < 2; kk++) {
            unsigned a[4][4];
            #pragma unroll
            for (int i = 0; i < 4; i++)
                ldsm4(a[i][0], a[i][1], a[i][2], a[i][3],
                      aB + i * 16 * HS2 + kk * 16);
            unsigned rb[8];
            ldsm4(rb[0], rb[1], rb[2], rb[3], bB + kk * 16);              // j=0,1
            ldsm4(rb[4], rb[5], rb[6], rb[7], bB + 16 * HS2 + kk * 16);   // j=2,3
            #pragma unroll
            for (int j = 0; j < 4; j++) {
                #pragma unroll
                for (int i = 0; i < 4; i++)
                    mma16h(c[i][j], a[i], rb[j * 2], rb[j * 2 + 1]);
            }
        }
        // no trailing sync: next iter's STS targets the other buffer, whose
        // last readers were iter kt-1 (separated by this iter's sync).
    }

    // ---- epilogue: direct STG from fragments, bias in registers ----
    #pragma unroll
    for (int j = 0; j < 4; j++) {
        const int col = n0 + wn * 32 + j * 8 + 2 * q4;
        const float2 bb = *(const float2*)&bias[col];
        #pragma unroll
        for (int i = 0; i < 4; i++) {
            const int row = m0 + wm * 64 + i * 16 + g4;
            float2 v0, v1;
            v0.x = (c[i][j][0] + bb.x) * scale;
            v0.y = (c[i][j][1] + bb.y) * scale;
            v1.x = (c[i][j][2] + bb.x) * scale;
            v1.y = (c[i][j][3] + bb.y) * scale;
            if (OM == 0) {
                float* C = (float*)Cv;
                *(float2*)&C[(size_t)row * D_MODEL + col] = v0;
                *(float2*)&C[(size_t)(row + 8) * D_MODEL + col] = v1;
            } else if (OM == 1) {
                __half* C = (__half*)Cv;
                *(__half2*)(C + (size_t)row * D_MODEL + col) =
                    __floats2half2_rn(v0.x, v0.y);
                *(__half2*)(C + (size_t)(row + 8) * D_MODEL + col) =
                    __floats2half2_rn(v1.x, v1.y);
            } else {
                __half* C = (__half*)Cv;
                const int b0i = row >> 11, tl0 = row & 2047;
                const int b1i = (row + 8) >> 11, tl1 = (row + 8) & 2047;
                C[((size_t)b0i * D_MODEL + col)     * SEQ + tl0] = __float2half_rn(v0.x);
                C[((size_t)b0i * D_MODEL + col + 1) * SEQ + tl0] = __float2half_rn(v0.y);
                C[((size_t)b1i * D_MODEL + col)     * SEQ + tl1] = __float2half_rn(v1.x);
                C[((size_t)b1i * D_MODEL + col + 1) * SEQ + tl1] = __float2half_rn(v1.y);
            }
        }
    }
}

// ---------------------------------------------------------------------------
// Flash attention (R13): fp16 mma.m16n8k16, fp32 accumulators/softmax.
// Q/K half [token][channel]; V half TRANSPOSED [b][channel][token].
// Output written as HALF (feeds the fp16 Wo GEMM).
// ---------------------------------------------------------------------------
#define HS 72
#define NTILES (SEQ / 64)
#define ATTN_SMEM ((128*HS + 2*64*HS + 2*64*HS) * (int)sizeof(__half))  // 55296

__global__ __launch_bounds__(256, 2) void attn_h(
    const __half* __restrict__ Qb, const __half* __restrict__ Kb,
    const __half* __restrict__ Vt, __half* __restrict__ Ob)
{
    extern __shared__ __half smh[];
    __half* Ps   = smh;                      // [128][HS]  (Q staging, then P)
    __half* Kbuf = Ps + 128 * HS;            // [2][64][HS]
    __half* Vbuf = Kbuf + 2 * 64 * HS;       // [2][64][HS]  rows = d, cols = token

    const int qt = blockIdx.x, h = blockIdx.y, b = blockIdx.z;
    const int t = threadIdx.x, w = t >> 5, lane = t & 31;
    const int g4 = lane >> 2, q4 = lane & 3;
    const int base_q = b * SEQ + qt * 128;
    const int hcol = h * HEAD_DIM;

    const int koff = ((lane & 7) + ((lane >> 4) << 3)) * HS + ((lane >> 3) & 1) * 8;
    const int poff = (lane & 15) * HS + (lane >> 4) * 8;

    const __half* Vbase = Vt + ((size_t)b * D_MODEL + hcol) * SEQ;

    {
        #pragma unroll
        for (int i = 0; i < 2; i++) {
            const int cid = t + i * 256;
            const int row = cid >> 3, seg = (cid & 7) * 8;
            cp_async16(&Kbuf[row * HS + seg],
                       Kb + (size_t)(b * SEQ + row) * D_MODEL + hcol + seg);
            cp_async16(&Vbuf[row * HS + seg],
                       Vbase + (size_t)row * SEQ + seg);
        }
    }
    CP_COMMIT();

    {
        const int r = t >> 1;
        const int c0 = (t & 1) * 32;
        #pragma unroll
        for (int i = 0; i < 4; i++)
            *(float4*)&Ps[r * HS + c0 + i * 8] =
                *(const float4*)(Qb + (size_t)(base_q + r) * D_MODEL + hcol + c0 + i * 8);
    }
    __syncwarp();

    unsigned qa[4][4];
    {
        const __half* qB = Ps + (w * 16) * HS + poff;
        #pragma unroll
        for (int kk = 0; kk < 4; kk++)
            ldsm4(qa[kk][0], qa[kk][1], qa[kk][2], qa[kk][3], qB + kk * 16);
    }
    __syncwarp();

    float of[8][4];
    #pragma unroll
    for (int n = 0; n < 8; n++)
        of[n][0] = of[n][1] = of[n][2] = of[n][3] = 0.f;
    float m0r = -1e30f, m1r = -1e30f, l0r = 0.f, l1r = 0.f;

    for (int jt = 0; jt < NTILES; jt++) {
        __half* Kc = Kbuf + (jt & 1) * 64 * HS;
        __half* Vc = Vbuf + (jt & 1) * 64 * HS;

        if (jt + 1 < NTILES) {
            __half* Kn = Kbuf + ((jt + 1) & 1) * 64 * HS;
            __half* Vn = Vbuf + ((jt + 1) & 1) * 64 * HS;
            const int tok0 = (jt + 1) * 64;
            #pragma unroll
            for (int i = 0; i < 2; i++) {
                const int cid = t + i * 256;
                const int row = cid >> 3, seg = (cid & 7) * 8;
                cp_async16(&Kn[row * HS + seg],
                           Kb + (size_t)(b * SEQ + tok0 + row) * D_MODEL + hcol + seg);
                cp_async16(&Vn[row * HS + seg],
                           Vbase + (size_t)row * SEQ + tok0 + seg);
            }
        }
        CP_COMMIT();
        CP_WAIT1();
        __syncthreads();

        float sfr[8][4];
        #pragma unroll
        for (int n = 0; n < 8; n++)
            sfr[n][0] = sfr[n][1] = sfr[n][2] = sfr[n][3] = 0.f;
        {
            const __half* kB = Kc + koff;
            #pragma unroll
            for (int kk = 0; kk < 4; kk++) {
                #pragma unroll
                for (int jp = 0; jp < 4; jp++) {
                    unsigned rb[4];
                    ldsm4(rb[0], rb[1], rb[2], rb[3], kB + jp * 16 * HS + kk * 16);
                    mma16h(sfr[jp * 2],     qa[kk], rb[0], rb[1]);
                    mma16h(sfr[jp * 2 + 1], qa[kk], rb[2], rb[3]);
                }
            }
        }

        float mx0 = -1e30f, mx1 = -1e30f;
        #pragma unroll
        for (int n = 0; n < 8; n++) {
            mx0 = fmaxf(mx0, fmaxf(sfr[n][0], sfr[n][1]));
            mx1 = fmaxf(mx1, fmaxf(sfr[n][2], sfr[n][3]));
        }
        mx0 = fmaxf(mx0, __shfl_xor_sync(0xffffffffu, mx0, 1));
        mx0 = fmaxf(mx0, __shfl_xor_sync(0xffffffffu, mx0, 2));
        mx1 = fmaxf(mx1, __shfl_xor_sync(0xffffffffu, mx1, 1));
        mx1 = fmaxf(mx1, __shfl_xor_sync(0xffffffffu, mx1, 2));

        const float mn0 = fmaxf(m0r, mx0);
        const float mn1 = fmaxf(m1r, mx1);
        const float a0 = __expf(m0r - mn0);
        const float a1 = __expf(m1r - mn1);
        m0r = mn0; m1r = mn1;

        float s0 = 0.f, s1 = 0.f;
        #pragma unroll
        for (int n = 0; n < 8; n++) {
            sfr[n][0] = __expf(sfr[n][0] - mn0);
            sfr[n][1] = __expf(sfr[n][1] - mn0);
            sfr[n][2] = __expf(sfr[n][2] - mn1);
            sfr[n][3] = __expf(sfr[n][3] - mn1);
            s0 += sfr[n][0] + sfr[n][1];
            s1 += sfr[n][2] + sfr[n][3];
            of[n][0] *= a0; of[n][1] *= a0;
            of[n][2] *= a1; of[n][3] *= a1;
            *(__half2*)&Ps[(w * 16 + g4)     * HS + n * 8 + 2 * q4] =
                __floats2half2_rn(sfr[n][0], sfr[n][1]);
            *(__half2*)&Ps[(w * 16 + g4 + 8) * HS + n * 8 + 2 * q4] =
                __floats2half2_rn(sfr[n][2], sfr[n][3]);
        }
        s0 += __shfl_xor_sync(0xffffffffu, s0, 1);
        s0 += __shfl_xor_sync(0xffffffffu, s0, 2);
        s1 += __shfl_xor_sync(0xffffffffu, s1, 1);
        s1 += __shfl_xor_sync(0xffffffffu, s1, 2);
        l0r = l0r * a0 + s0;
        l1r = l1r * a1 + s1;
        __syncwarp();

        {
            const __half* pB = Ps + (w * 16) * HS + poff;
            const __half* vB = Vc + koff;
            #pragma unroll
            for (int kk = 0; kk < 4; kk++) {
                unsigned pa[4];
                ldsm4(pa[0], pa[1], pa[2], pa[3], pB + kk * 16);
                #pragma unroll
                for (int jp = 0; jp < 4; jp++) {
                    unsigned rb[4];
                    ldsm4(rb[0], rb[1], rb[2], rb[3], vB + jp * 16 * HS + kk * 16);
                    mma16h(of[jp * 2],     pa, rb[0], rb[1]);
                    mma16h(of[jp * 2 + 1], pa, rb[2], rb[3]);
                }
            }
        }
        __syncwarp();
        __syncthreads();
    }

    // ---- epilogue: normalize, write HALF [B,T,H*hd] ----
    const float inv0 = 1.f / l0r;
    const float inv1 = 1.f / l1r;
    const int r0 = base_q + w * 16 + g4;
    #pragma unroll
    for (int n = 0; n < 8; n++) {
        const int c = hcol + n * 8 + 2 * q4;
        *(__half2*)(Ob + (size_t)r0 * D_MODEL + c) =
            __floats2half2_rn(of[n][0] * inv0, of[n][1] * inv0);
        *(__half2*)(Ob + (size_t)(r0 + 8) * D_MODEL + c) =
            __floats2half2_rn(of[n][2] * inv1, of[n][3] * inv1);
    }
}

// ---------------------------------------------------------------------------
extern "C" void kernel_launch(void* const* d_in, const int* in_sizes, int n_in,
                              void* d_out, int out_size)
{
    const float* query = (const float*)d_in[0];
    const float* key   = (const float*)d_in[1];
    const float* value = (const float*)d_in[2];
    const float* Wq    = (const float*)d_in[3];
    const float* bq    = (const float*)d_in[4];
    const float* Wk    = (const float*)d_in[5];
    const float* bk    = (const float*)d_in[6];
    const float* Wv    = (const float*)d_in[7];
    const float* bv    = (const float*)d_in[8];
    const float* Wo    = (const float*)d_in[9];
    const float* bo    = (const float*)d_in[10];
    float* out = (float*)d_out;

    __half *pQ, *pK, *pVt, *pA;
    cudaGetSymbolAddress((void**)&pQ, g_Q);
    cudaGetSymbolAddress((void**)&pK, g_K);
    cudaGetSymbolAddress((void**)&pVt, g_Vt);
    cudaGetSymbolAddress((void**)&pA, g_Attn);

    cudaFuncSetAttribute((const void*)gemm_h<float, 1>,
                         cudaFuncAttributeMaxDynamicSharedMemorySize, GEMMH_SMEM);
    cudaFuncSetAttribute((const void*)gemm_h<float, 2>,
                         cudaFuncAttributeMaxDynamicSharedMemorySize, GEMMH_SMEM);
    cudaFuncSetAttribute((const void*)gemm_h<__half, 0>,
                         cudaFuncAttributeMaxDynamicSharedMemorySize, GEMMH_SMEM);
    cudaFuncSetAttribute((const void*)attn_h,
                         cudaFuncAttributeMaxDynamicSharedMemorySize, ATTN_SMEM);

    dim3 gemm_grid(D_MODEL / 128, MTOT / 128);   // (8, 32)
    const float qscale = 0.125f;                 // 1/sqrt(64)

    gemm_h<float, 1><<<gemm_grid, 256, GEMMH_SMEM>>>(query, Wq, bq, qscale, pQ);
    gemm_h<float, 1><<<gemm_grid, 256, GEMMH_SMEM>>>(key,   Wk, bk, 1.f,    pK);
    gemm_h<float, 2><<<gemm_grid, 256, GEMMH_SMEM>>>(value, Wv, bv, 1.f,    pVt);

    dim3 attn_grid(SEQ / 128, NHEAD, BATCH);     // (16, 16, 2)
    attn_h<<<attn_grid, 256, ATTN_SMEM>>>(pQ, pK, pVt, pA);

    gemm_h<__half, 0><<<gemm_grid, 256, GEMMH_SMEM>>>(pA, Wo, bo, 1.f, out);
}

// round 15
// speedup vs baseline: 2.1797x; 1.2686x over previous
#include <cuda_runtime.h>
#include <cuda_fp16.h>
#include <cstdint>
#include <math.h>

#define D_MODEL 1024
#define NHEAD 16
#define HEAD_DIM 64
#define BATCH 2
#define SEQ 2048
#define MTOT (BATCH*SEQ)   // 4096

// Scratch (allocation-free rule: __device__ globals)
__device__ __half g_Q[MTOT * D_MODEL];
__device__ __half g_K[MTOT * D_MODEL];
__device__ __half g_Vt[MTOT * D_MODEL];  // V projection, TRANSPOSED: [b][channel][token]
__device__ __half g_Attn[MTOT * D_MODEL];
// half pre-conversions of inputs / weights
__device__ __half g_hXq[MTOT * D_MODEL];
__device__ __half g_hXk[MTOT * D_MODEL];
__device__ __half g_hXv[MTOT * D_MODEL];
__device__ __half g_hWq[D_MODEL * D_MODEL];
__device__ __half g_hWk[D_MODEL * D_MODEL];
__device__ __half g_hWv[D_MODEL * D_MODEL];
__device__ __half g_hWo[D_MODEL * D_MODEL];

// ---------------------------------------------------------------------------
// helpers
// ---------------------------------------------------------------------------
__device__ __forceinline__ void mma16h(float* c, const unsigned* a,
                                       unsigned b0, unsigned b1) {
    asm volatile(
        "mma.sync.aligned.m16n8k16.row.col.f32.f16.f16.f32 "
        "{%0,%1,%2,%3}, {%4,%5,%6,%7}, {%8,%9}, {%0,%1,%2,%3};"
        : "+f"(c[0]), "+f"(c[1]), "+f"(c[2]), "+f"(c[3])
        : "r"(a[0]), "r"(a[1]), "r"(a[2]), "r"(a[3]), "r"(b0), "r"(b1));
}

__device__ __forceinline__ void ldsm4(unsigned& r0, unsigned& r1,
                                      unsigned& r2, unsigned& r3, const void* p) {
    unsigned addr = (unsigned)__cvta_generic_to_shared(p);
    asm volatile("ldmatrix.sync.aligned.m8n8.x4.shared.b16 {%0,%1,%2,%3}, [%4];"
        : "=r"(r0), "=r"(r1), "=r"(r2), "=r"(r3) : "r"(addr));
}

__device__ __forceinline__ void cp_async16(void* dst, const void* src) {
    unsigned int d = (unsigned int)__cvta_generic_to_shared(dst);
    asm volatile("cp.async.cg.shared.global [%0], [%1], 16;" :: "r"(d), "l"(src));
}
#define CP_COMMIT() asm volatile("cp.async.commit_group;")
#define CP_WAIT0()  asm volatile("cp.async.wait_group 0;")
#define CP_WAIT1()  asm volatile("cp.async.wait_group 1;")

// ---------------------------------------------------------------------------
// f32 -> f16 conversion passes (rn, bit-identical to old staging cvts)
// ---------------------------------------------------------------------------
__global__ void f2h3(const float* __restrict__ s0, const float* __restrict__ s1,
                     const float* __restrict__ s2, __half* __restrict__ d0,
                     __half* __restrict__ d1, __half* __restrict__ d2)
{
    const float* s = blockIdx.z == 0 ? s0 : blockIdx.z == 1 ? s1 : s2;
    __half* d = blockIdx.z == 0 ? d0 : blockIdx.z == 1 ? d1 : d2;
    const int i = blockIdx.x * blockDim.x + threadIdx.x;
    float4 a = ((const float4*)s)[2 * i];
    float4 b = ((const float4*)s)[2 * i + 1];
    __half2 h[4] = { __floats2half2_rn(a.x, a.y), __floats2half2_rn(a.z, a.w),
                     __floats2half2_rn(b.x, b.y), __floats2half2_rn(b.z, b.w) };
    ((float4*)d)[i] = *(float4*)h;
}

__global__ void f2h4(const float* __restrict__ s0, const float* __restrict__ s1,
                     const float* __restrict__ s2, const float* __restrict__ s3,
                     __half* __restrict__ d0, __half* __restrict__ d1,
                     __half* __restrict__ d2, __half* __restrict__ d3)
{
    const float* s = blockIdx.z == 0 ? s0 : blockIdx.z == 1 ? s1
                   : blockIdx.z == 2 ? s2 : s3;
    __half* d = blockIdx.z == 0 ? d0 : blockIdx.z == 1 ? d1
              : blockIdx.z == 2 ? d2 : d3;
    const int i = blockIdx.x * blockDim.x + threadIdx.x;
    float4 a = ((const float4*)s)[2 * i];
    float4 b = ((const float4*)s)[2 * i + 1];
    __half2 h[4] = { __floats2half2_rn(a.x, a.y), __floats2half2_rn(a.z, a.w),
                     __floats2half2_rn(b.x, b.y), __floats2half2_rn(b.z, b.w) };
    ((float4*)d)[i] = *(float4*)h;
}

// ---------------------------------------------------------------------------
// fp16 GEMM, cp.async half staging:  C = (A @ W^T + bias) * scale
// A and W are pre-converted half. Per thread per k-tile: 4 cp.async.16B,
// zero LDG/cvt/STS. Single cp.async group in flight; wait0 -> sync ->
// issue next tile (overlaps compute, WAR-safe behind the sync) -> compute.
// OM: 0 = f32 [token][channel], 1 = half [token][channel],
//     2 = half TRANSPOSED [b][channel][token] (Vt)
// 128x128 block, BK=32, 8 warps (2x4), warp tile 64x32, mma.m16n8k16.
// smem stride 40 halves: ldmatrix phases conflict-free (R14-proven).
// ---------------------------------------------------------------------------
#define HS2 40
#define GEMMH_SMEM (4 * 128 * HS2 * (int)sizeof(__half))   // 40960 bytes

template<int OM>
__global__ __launch_bounds__(256, 2) void gemm_hcp(
    const __half* __restrict__ A, const __half* __restrict__ W,
    const float* __restrict__ bias, float scale, void* __restrict__ Cv)
{
    extern __shared__ __half smh[];
    __half* As = smh;                   // [2][128*HS2]
    __half* Ws = smh + 2 * 128 * HS2;   // [2][128*HS2]

    const int m0 = blockIdx.y * 128;
    const int n0 = blockIdx.x * 128;
    const int t  = threadIdx.x;
    const int wid = t >> 5, lane = t & 31;
    const int g4 = lane >> 2, q4 = lane & 3;
    const int wm = wid >> 2;          // 0..1
    const int wn = wid & 3;           // 0..3

    float c[4][4][4];
    #pragma unroll
    for (int i = 0; i < 4; i++)
        #pragma unroll
        for (int j = 0; j < 4; j++)
            c[i][j][0] = c[i][j][1] = c[i][j][2] = c[i][j][3] = 0.f;

    // ldmatrix per-lane offsets (half units)
    const int aoff = (lane & 15) * HS2 + (lane >> 4) * 8;
    const int boff = ((lane & 7) + ((lane >> 4) << 3)) * HS2 + ((lane >> 3) & 1) * 8;

    const int NKT = D_MODEL / 32;

    // stage k-tile kt into buffer kt&1 (4 cp.async per thread)
    auto stage = [&](int kt) {
        __half* Ab = As + (kt & 1) * 128 * HS2;
        __half* Wb = Ws + (kt & 1) * 128 * HS2;
        const int ke = kt * 32;
        #pragma unroll
        for (int i = 0; i < 2; i++) {
            const int cid = t + i * 256;            // 0..511
            const int row = cid >> 2, seg = (cid & 3) * 8;
            cp_async16(&Ab[row * HS2 + seg],
                       A + (size_t)(m0 + row) * D_MODEL + ke + seg);
            cp_async16(&Wb[row * HS2 + seg],
                       W + (size_t)(n0 + row) * D_MODEL + ke + seg);
        }
    };

    stage(0);
    CP_COMMIT();

    for (int kt = 0; kt < NKT; kt++) {
        CP_WAIT0();          // tile kt resident (single group in flight)
        __syncthreads();     // visibility + all readers of buf (kt+1)&1 done
        if (kt + 1 < NKT) {
            stage(kt + 1);   // overlaps the compute below
            CP_COMMIT();
        }

        const __half* aB = As + (kt & 1) * 128 * HS2 + (wm * 64) * HS2 + aoff;
        const __half* bB = Ws + (kt & 1) * 128 * HS2 + (wn * 32) * HS2 + boff;
        #pragma unroll
        for (int kk = 0; kk < 2; kk++) {
            unsigned a[4][4];
            #pragma unroll
            for (int i = 0; i < 4; i++)
                ldsm4(a[i][0], a[i][1], a[i][2], a[i][3],
                      aB + i * 16 * HS2 + kk * 16);
            unsigned rb[8];
            ldsm4(rb[0], rb[1], rb[2], rb[3], bB + kk * 16);              // j=0,1
            ldsm4(rb[4], rb[5], rb[6], rb[7], bB + 16 * HS2 + kk * 16);   // j=2,3
            #pragma unroll
            for (int j = 0; j < 4; j++) {
                #pragma unroll
                for (int i = 0; i < 4; i++)
                    mma16h(c[i][j], a[i], rb[j * 2], rb[j * 2 + 1]);
            }
        }
    }

    // ---- epilogue: direct STG from fragments, bias in registers ----
    #pragma unroll
    for (int j = 0; j < 4; j++) {
        const int col = n0 + wn * 32 + j * 8 + 2 * q4;
        const float2 bb = *(const float2*)&bias[col];
        #pragma unroll
        for (int i = 0; i < 4; i++) {
            const int row = m0 + wm * 64 + i * 16 + g4;
            float2 v0, v1;
            v0.x = (c[i][j][0] + bb.x) * scale;
            v0.y = (c[i][j][1] + bb.y) * scale;
            v1.x = (c[i][j][2] + bb.x) * scale;
            v1.y = (c[i][j][3] + bb.y) * scale;
            if (OM == 0) {
                float* C = (float*)Cv;
                *(float2*)&C[(size_t)row * D_MODEL + col] = v0;
                *(float2*)&C[(size_t)(row + 8) * D_MODEL + col] = v1;
            } else if (OM == 1) {
                __half* C = (__half*)Cv;
                *(__half2*)(C + (size_t)row * D_MODEL + col) =
                    __floats2half2_rn(v0.x, v0.y);
                *(__half2*)(C + (size_t)(row + 8) * D_MODEL + col) =
                    __floats2half2_rn(v1.x, v1.y);
            } else {
                __half* C = (__half*)Cv;
                const int b0i = row >> 11, tl0 = row & 2047;
                const int b1i = (row + 8) >> 11, tl1 = (row + 8) & 2047;
                C[((size_t)b0i * D_MODEL + col)     * SEQ + tl0] = __float2half_rn(v0.x);
                C[((size_t)b0i * D_MODEL + col + 1) * SEQ + tl0] = __float2half_rn(v0.y);
                C[((size_t)b1i * D_MODEL + col)     * SEQ + tl1] = __float2half_rn(v1.x);
                C[((size_t)b1i * D_MODEL + col + 1) * SEQ + tl1] = __float2half_rn(v1.y);
            }
        }
    }
}

// ---------------------------------------------------------------------------
// Flash attention (R13/14, unchanged): fp16 mma.m16n8k16, fp32 softmax.
// ---------------------------------------------------------------------------
#define HS 72
#define NTILES (SEQ / 64)
#define ATTN_SMEM ((128*HS + 2*64*HS + 2*64*HS) * (int)sizeof(__half))  // 55296

__global__ __launch_bounds__(256, 2) void attn_h(
    const __half* __restrict__ Qb, const __half* __restrict__ Kb,
    const __half* __restrict__ Vt, __half* __restrict__ Ob)
{
    extern __shared__ __half smh[];
    __half* Ps   = smh;                      // [128][HS]  (Q staging, then P)
    __half* Kbuf = Ps + 128 * HS;            // [2][64][HS]
    __half* Vbuf = Kbuf + 2 * 64 * HS;       // [2][64][HS]

    const int qt = blockIdx.x, h = blockIdx.y, b = blockIdx.z;
    const int t = threadIdx.x, w = t >> 5, lane = t & 31;
    const int g4 = lane >> 2, q4 = lane & 3;
    const int base_q = b * SEQ + qt * 128;
    const int hcol = h * HEAD_DIM;

    const int koff = ((lane & 7) + ((lane >> 4) << 3)) * HS + ((lane >> 3) & 1) * 8;
    const int poff = (lane & 15) * HS + (lane >> 4) * 8;

    const __half* Vbase = Vt + ((size_t)b * D_MODEL + hcol) * SEQ;

    {
        #pragma unroll
        for (int i = 0; i < 2; i++) {
            const int cid = t + i * 256;
            const int row = cid >> 3, seg = (cid & 7) * 8;
            cp_async16(&Kbuf[row * HS + seg],
                       Kb + (size_t)(b * SEQ + row) * D_MODEL + hcol + seg);
            cp_async16(&Vbuf[row * HS + seg],
                       Vbase + (size_t)row * SEQ + seg);
        }
    }
    CP_COMMIT();

    {
        const int r = t >> 1;
        const int c0 = (t & 1) * 32;
        #pragma unroll
        for (int i = 0; i < 4; i++)
            *(float4*)&Ps[r * HS + c0 + i * 8] =
                *(const float4*)(Qb + (size_t)(base_q + r) * D_MODEL + hcol + c0 + i * 8);
    }
    __syncwarp();

    unsigned qa[4][4];
    {
        const __half* qB = Ps + (w * 16) * HS + poff;
        #pragma unroll
        for (int kk = 0; kk < 4; kk++)
            ldsm4(qa[kk][0], qa[kk][1], qa[kk][2], qa[kk][3], qB + kk * 16);
    }
    __syncwarp();

    float of[8][4];
    #pragma unroll
    for (int n = 0; n < 8; n++)
        of[n][0] = of[n][1] = of[n][2] = of[n][3] = 0.f;
    float m0r = -1e30f, m1r = -1e30f, l0r = 0.f, l1r = 0.f;

    for (int jt = 0; jt < NTILES; jt++) {
        __half* Kc = Kbuf + (jt & 1) * 64 * HS;
        __half* Vc = Vbuf + (jt & 1) * 64 * HS;

        if (jt + 1 < NTILES) {
            __half* Kn = Kbuf + ((jt + 1) & 1) * 64 * HS;
            __half* Vn = Vbuf + ((jt + 1) & 1) * 64 * HS;
            const int tok0 = (jt + 1) * 64;
            #pragma unroll
            for (int i = 0; i < 2; i++) {
                const int cid = t + i * 256;
                const int row = cid >> 3, seg = (cid & 7) * 8;
                cp_async16(&Kn[row * HS + seg],
                           Kb + (size_t)(b * SEQ + tok0 + row) * D_MODEL + hcol + seg);
                cp_async16(&Vn[row * HS + seg],
                           Vbase + (size_t)row * SEQ + tok0 + seg);
            }
        }
        CP_COMMIT();
        CP_WAIT1();
        __syncthreads();

        float sfr[8][4];
        #pragma unroll
        for (int n = 0; n < 8; n++)
            sfr[n][0] = sfr[n][1] = sfr[n][2] = sfr[n][3] = 0.f;
        {
            const __half* kB = Kc + koff;
            #pragma unroll
            for (int kk = 0; kk < 4; kk++) {
                #pragma unroll
                for (int jp = 0; jp < 4; jp++) {
                    unsigned rb[4];
                    ldsm4(rb[0], rb[1], rb[2], rb[3], kB + jp * 16 * HS + kk * 16);
                    mma16h(sfr[jp * 2],     qa[kk], rb[0], rb[1]);
                    mma16h(sfr[jp * 2 + 1], qa[kk], rb[2], rb[3]);
                }
            }
        }

        float mx0 = -1e30f, mx1 = -1e30f;
        #pragma unroll
        for (int n = 0; n < 8; n++) {
            mx0 = fmaxf(mx0, fmaxf(sfr[n][0], sfr[n][1]));
            mx1 = fmaxf(mx1, fmaxf(sfr[n][2], sfr[n][3]));
        }
        mx0 = fmaxf(mx0, __shfl_xor_sync(0xffffffffu, mx0, 1));
        mx0 = fmaxf(mx0, __shfl_xor_sync(0xffffffffu, mx0, 2));
        mx1 = fmaxf(mx1, __shfl_xor_sync(0xffffffffu, mx1, 1));
        mx1 = fmaxf(mx1, __shfl_xor_sync(0xffffffffu, mx1, 2));

        const float mn0 = fmaxf(m0r, mx0);
        const float mn1 = fmaxf(m1r, mx1);
        const float a0 = __expf(m0r - mn0);
        const float a1 = __expf(m1r - mn1);
        m0r = mn0; m1r = mn1;

        float s0 = 0.f, s1 = 0.f;
        #pragma unroll
        for (int n = 0; n < 8; n++) {
            sfr[n][0] = __expf(sfr[n][0] - mn0);
            sfr[n][1] = __expf(sfr[n][1] - mn0);
            sfr[n][2] = __expf(sfr[n][2] - mn1);
            sfr[n][3] = __expf(sfr[n][3] - mn1);
            s0 += sfr[n][0] + sfr[n][1];
            s1 += sfr[n][2] + sfr[n][3];
            of[n][0] *= a0; of[n][1] *= a0;
            of[n][2] *= a1; of[n][3] *= a1;
            *(__half2*)&Ps[(w * 16 + g4)     * HS + n * 8 + 2 * q4] =
                __floats2half2_rn(sfr[n][0], sfr[n][1]);
            *(__half2*)&Ps[(w * 16 + g4 + 8) * HS + n * 8 + 2 * q4] =
                __floats2half2_rn(sfr[n][2], sfr[n][3]);
        }
        s0 += __shfl_xor_sync(0xffffffffu, s0, 1);
        s0 += __shfl_xor_sync(0xffffffffu, s0, 2);
        s1 += __shfl_xor_sync(0xffffffffu, s1, 1);
        s1 += __shfl_xor_sync(0xffffffffu, s1, 2);
        l0r = l0r * a0 + s0;
        l1r = l1r * a1 + s1;
        __syncwarp();

        {
            const __half* pB = Ps + (w * 16) * HS + poff;
            const __half* vB = Vc + koff;
            #pragma unroll
            for (int kk = 0; kk < 4; kk++) {
                unsigned pa[4];
                ldsm4(pa[0], pa[1], pa[2], pa[3], pB + kk * 16);
                #pragma unroll
                for (int jp = 0; jp < 4; jp++) {
                    unsigned rb[4];
                    ldsm4(rb[0], rb[1], rb[2], rb[3], vB + jp * 16 * HS + kk * 16);
                    mma16h(of[jp * 2],     pa, rb[0], rb[1]);
                    mma16h(of[jp * 2 + 1], pa, rb[2], rb[3]);
                }
            }
        }
        __syncwarp();
        __syncthreads();
    }

    const float inv0 = 1.f / l0r;
    const float inv1 = 1.f / l1r;
    const int r0 = base_q + w * 16 + g4;
    #pragma unroll
    for (int n = 0; n < 8; n++) {
        const int c = hcol + n * 8 + 2 * q4;
        *(__half2*)(Ob + (size_t)r0 * D_MODEL + c) =
            __floats2half2_rn(of[n][0] * inv0, of[n][1] * inv0);
        *(__half2*)(Ob + (size_t)(r0 + 8) * D_MODEL + c) =
            __floats2half2_rn(of[n][2] * inv1, of[n][3] * inv1);
    }
}

// ---------------------------------------------------------------------------
extern "C" void kernel_launch(void* const* d_in, const int* in_sizes, int n_in,
                              void* d_out, int out_size)
{
    const float* query = (const float*)d_in[0];
    const float* key   = (const float*)d_in[1];
    const float* value = (const float*)d_in[2];
    const float* Wq    = (const float*)d_in[3];
    const float* bq    = (const float*)d_in[4];
    const float* Wk    = (const float*)d_in[5];
    const float* bk    = (const float*)d_in[6];
    const float* Wv    = (const float*)d_in[7];
    const float* bv    = (const float*)d_in[8];
    const float* Wo    = (const float*)d_in[9];
    const float* bo    = (const float*)d_in[10];
    float* out = (float*)d_out;

    __half *pQ, *pK, *pVt, *pA;
    __half *hXq, *hXk, *hXv, *hWq, *hWk, *hWv, *hWo;
    cudaGetSymbolAddress((void**)&pQ, g_Q);
    cudaGetSymbolAddress((void**)&pK, g_K);
    cudaGetSymbolAddress((void**)&pVt, g_Vt);
    cudaGetSymbolAddress((void**)&pA, g_Attn);
    cudaGetSymbolAddress((void**)&hXq, g_hXq);
    cudaGetSymbolAddress((void**)&hXk, g_hXk);
    cudaGetSymbolAddress((void**)&hXv, g_hXv);
    cudaGetSymbolAddress((void**)&hWq, g_hWq);
    cudaGetSymbolAddress((void**)&hWk, g_hWk);
    cudaGetSymbolAddress((void**)&hWv, g_hWv);
    cudaGetSymbolAddress((void**)&hWo, g_hWo);

    cudaFuncSetAttribute((const void*)gemm_hcp<0>,
                         cudaFuncAttributeMaxDynamicSharedMemorySize, GEMMH_SMEM);
    cudaFuncSetAttribute((const void*)gemm_hcp<1>,
                         cudaFuncAttributeMaxDynamicSharedMemorySize, GEMMH_SMEM);
    cudaFuncSetAttribute((const void*)gemm_hcp<2>,
                         cudaFuncAttributeMaxDynamicSharedMemorySize, GEMMH_SMEM);
    cudaFuncSetAttribute((const void*)attn_h,
                         cudaFuncAttributeMaxDynamicSharedMemorySize, ATTN_SMEM);

    // --- f32 -> f16 pre-conversions ---
    dim3 cg3((MTOT * D_MODEL / 8) / 256, 1, 3);     // (2048, 1, 3)
    dim3 cg4((D_MODEL * D_MODEL / 8) / 256, 1, 4);  // (512, 1, 4)
    f2h3<<<cg3, 256>>>(query, key, value, hXq, hXk, hXv);
    f2h4<<<cg4, 256>>>(Wq, Wk, Wv, Wo, hWq, hWk, hWv, hWo);

    dim3 gemm_grid(D_MODEL / 128, MTOT / 128);   // (8, 32)
    const float qscale = 0.125f;                 // 1/sqrt(64)

    gemm_hcp<1><<<gemm_grid, 256, GEMMH_SMEM>>>(hXq, hWq, bq, qscale, pQ);
    gemm_hcp<1><<<gemm_grid, 256, GEMMH_SMEM>>>(hXk, hWk, bk, 1.f,    pK);
    gemm_hcp<2><<<gemm_grid, 256, GEMMH_SMEM>>>(hXv, hWv, bv, 1.f,    pVt);

    dim3 attn_grid(SEQ / 128, NHEAD, BATCH);     // (16, 16, 2)
    attn_h<<<attn_grid, 256, ATTN_SMEM>>>(pQ, pK, pVt, pA);

    gemm_hcp<0><<<gemm_grid, 256, GEMMH_SMEM>>>(pA, hWo, bo, 1.f, out);
}

// round 16
// speedup vs baseline: 2.2410x; 1.0281x over previous
#include <cuda_runtime.h>
#include <cuda_fp16.h>
#include <cstdint>
#include <math.h>

#define D_MODEL 1024
#define NHEAD 16
#define HEAD_DIM 64
#define BATCH 2
#define SEQ 2048
#define MTOT (BATCH*SEQ)   // 4096

// Scratch (allocation-free rule: __device__ globals)
__device__ __half g_Q[MTOT * D_MODEL];
__device__ __half g_K[MTOT * D_MODEL];
__device__ __half g_Vt[MTOT * D_MODEL];  // V projection, TRANSPOSED: [b][channel][token]
__device__ __half g_Attn[MTOT * D_MODEL];
// half pre-conversions of inputs / weights
__device__ __half g_hXq[MTOT * D_MODEL];
__device__ __half g_hXk[MTOT * D_MODEL];
__device__ __half g_hXv[MTOT * D_MODEL];
__device__ __half g_hWq[D_MODEL * D_MODEL];
__device__ __half g_hWk[D_MODEL * D_MODEL];
__device__ __half g_hWv[D_MODEL * D_MODEL];
__device__ __half g_hWo[D_MODEL * D_MODEL];

// ---------------------------------------------------------------------------
// helpers
// ---------------------------------------------------------------------------
__device__ __forceinline__ void mma16h(float* c, const unsigned* a,
                                       unsigned b0, unsigned b1) {
    asm volatile(
        "mma.sync.aligned.m16n8k16.row.col.f32.f16.f16.f32 "
        "{%0,%1,%2,%3}, {%4,%5,%6,%7}, {%8,%9}, {%0,%1,%2,%3};"
        : "+f"(c[0]), "+f"(c[1]), "+f"(c[2]), "+f"(c[3])
        : "r"(a[0]), "r"(a[1]), "r"(a[2]), "r"(a[3]), "r"(b0), "r"(b1));
}

__device__ __forceinline__ void ldsm4(unsigned& r0, unsigned& r1,
                                      unsigned& r2, unsigned& r3, const void* p) {
    unsigned addr = (unsigned)__cvta_generic_to_shared(p);
    asm volatile("ldmatrix.sync.aligned.m8n8.x4.shared.b16 {%0,%1,%2,%3}, [%4];"
        : "=r"(r0), "=r"(r1), "=r"(r2), "=r"(r3) : "r"(addr));
}

__device__ __forceinline__ void cp_async16(void* dst, const void* src) {
    unsigned int d = (unsigned int)__cvta_generic_to_shared(dst);
    asm volatile("cp.async.cg.shared.global [%0], [%1], 16;" :: "r"(d), "l"(src));
}
#define CP_COMMIT() asm volatile("cp.async.commit_group;")
#define CP_WAIT1()  asm volatile("cp.async.wait_group 1;")

// ---------------------------------------------------------------------------
// f32 -> f16 conversion, all 7 tensors in one launch (z = 0..6).
// z 0..2: inputs (MTOT*D_MODEL); z 3..6: weights (D_MODEL*D_MODEL).
// ---------------------------------------------------------------------------
__global__ void f2h_all(
    const float* __restrict__ x0, const float* __restrict__ x1,
    const float* __restrict__ x2, const float* __restrict__ w0,
    const float* __restrict__ w1, const float* __restrict__ w2,
    const float* __restrict__ w3,
    __half* __restrict__ y0, __half* __restrict__ y1, __half* __restrict__ y2,
    __half* __restrict__ v0, __half* __restrict__ v1, __half* __restrict__ v2,
    __half* __restrict__ v3)
{
    const int z = blockIdx.z;
    if (z >= 3 && blockIdx.x >= (D_MODEL * D_MODEL / 8) / 256) return;
    const float* s; __half* d;
    switch (z) {
        case 0: s = x0; d = y0; break;
        case 1: s = x1; d = y1; break;
        case 2: s = x2; d = y2; break;
        case 3: s = w0; d = v0; break;
        case 4: s = w1; d = v1; break;
        case 5: s = w2; d = v2; break;
        default: s = w3; d = v3; break;
    }
    const int i = blockIdx.x * blockDim.x + threadIdx.x;
    float4 a = ((const float4*)s)[2 * i];
    float4 b = ((const float4*)s)[2 * i + 1];
    __half2 h[4] = { __floats2half2_rn(a.x, a.y), __floats2half2_rn(a.z, a.w),
                     __floats2half2_rn(b.x, b.y), __floats2half2_rn(b.z, b.w) };
    ((float4*)d)[i] = *(float4*)h;
}

// ---------------------------------------------------------------------------
// fp16 GEMM, 3-buffer cp.async ring (wait_group 1):
//   C = (A @ W^T + bias) * scale     (fp32 accumulators)
// Per thread per k-tile: 4 cp.async.16B; compute always overlaps a load in
// flight. One __syncthreads per tile; commit EVERY iteration (empty group
// near the end) to keep wait-group counting consistent.
// OM: 0 = f32 [token][channel], 1 = half [token][channel],
//     2 = half TRANSPOSED [b][channel][token] (Vt)
// 128x128 block, BK=32, 8 warps (2x4), warp tile 64x32, mma.m16n8k16.
// smem stride 40 halves: ldmatrix phases conflict-free (R14-proven).
// ---------------------------------------------------------------------------
#define HS2 40
#define GEMMH_SMEM (6 * 128 * HS2 * (int)sizeof(__half))   // 61440 bytes

template<int OM>
__global__ __launch_bounds__(256, 2) void gemm_hcp(
    const __half* __restrict__ A, const __half* __restrict__ W,
    const float* __restrict__ bias, float scale, void* __restrict__ Cv)
{
    extern __shared__ __half smh[];
    __half* As = smh;                   // [3][128*HS2]
    __half* Ws = smh + 3 * 128 * HS2;   // [3][128*HS2]

    const int m0 = blockIdx.y * 128;
    const int n0 = blockIdx.x * 128;
    const int t  = threadIdx.x;
    const int wid = t >> 5, lane = t & 31;
    const int g4 = lane >> 2, q4 = lane & 3;
    const int wm = wid >> 2;          // 0..1
    const int wn = wid & 3;           // 0..3

    float c[4][4][4];
    #pragma unroll
    for (int i = 0; i < 4; i++)
        #pragma unroll
        for (int j = 0; j < 4; j++)
            c[i][j][0] = c[i][j][1] = c[i][j][2] = c[i][j][3] = 0.f;

    // ldmatrix per-lane offsets (half units)
    const int aoff = (lane & 15) * HS2 + (lane >> 4) * 8;
    const int boff = ((lane & 7) + ((lane >> 4) << 3)) * HS2 + ((lane >> 3) & 1) * 8;

    const int NKT = D_MODEL / 32;

    // stage k-tile kt into ring buffer b3 (4 cp.async per thread)
    auto stage = [&](int kt, int b3) {
        __half* Ab = As + b3 * 128 * HS2;
        __half* Wb = Ws + b3 * 128 * HS2;
        const int ke = kt * 32;
        #pragma unroll
        for (int i = 0; i < 2; i++) {
            const int cid = t + i * 256;            // 0..511
            const int row = cid >> 2, seg = (cid & 3) * 8;
            cp_async16(&Ab[row * HS2 + seg],
                       A + (size_t)(m0 + row) * D_MODEL + ke + seg);
            cp_async16(&Wb[row * HS2 + seg],
                       W + (size_t)(n0 + row) * D_MODEL + ke + seg);
        }
    };

    stage(0, 0); CP_COMMIT();
    stage(1, 1); CP_COMMIT();

    int buf = 0;
    for (int kt = 0; kt < NKT; kt++) {
        CP_WAIT1();          // tile kt resident; kt+1 still in flight
        __syncthreads();     // readers of buf (kt+2)%3 (from iter kt-1) done

        // stage tile kt+2; ALWAYS commit to keep group counting consistent
        const int nb = (buf + 2 >= 3) ? buf - 1 : buf + 2;
        if (kt + 2 < NKT) stage(kt + 2, nb);
        CP_COMMIT();

        const __half* aB = As + buf * 128 * HS2 + (wm * 64) * HS2 + aoff;
        const __half* bB = Ws + buf * 128 * HS2 + (wn * 32) * HS2 + boff;
        #pragma unroll
        for (int kk = 0; kk < 2; kk++) {
            unsigned a[4][4];
            #pragma unroll
            for (int i = 0; i < 4; i++)
                ldsm4(a[i][0], a[i][1], a[i][2], a[i][3],
                      aB + i * 16 * HS2 + kk * 16);
            unsigned rb[8];
            ldsm4(rb[0], rb[1], rb[2], rb[3], bB + kk * 16);              // j=0,1
            ldsm4(rb[4], rb[5], rb[6], rb[7], bB + 16 * HS2 + kk * 16);   // j=2,3
            #pragma unroll
            for (int j = 0; j < 4; j++) {
                #pragma unroll
                for (int i = 0; i < 4; i++)
                    mma16h(c[i][j], a[i], rb[j * 2], rb[j * 2 + 1]);
            }
        }
        buf = (buf + 1 == 3) ? 0 : buf + 1;
    }

    // ---- epilogue: direct STG from fragments, bias in registers ----
    #pragma unroll
    for (int j = 0; j < 4; j++) {
        const int col = n0 + wn * 32 + j * 8 + 2 * q4;
        const float2 bb = *(const float2*)&bias[col];
        #pragma unroll
        for (int i = 0; i < 4; i++) {
            const int row = m0 + wm * 64 + i * 16 + g4;
            float2 v0, v1;
            v0.x = (c[i][j][0] + bb.x) * scale;
            v0.y = (c[i][j][1] + bb.y) * scale;
            v1.x = (c[i][j][2] + bb.x) * scale;
            v1.y = (c[i][j][3] + bb.y) * scale;
            if (OM == 0) {
                float* C = (float*)Cv;
                *(float2*)&C[(size_t)row * D_MODEL + col] = v0;
                *(float2*)&C[(size_t)(row + 8) * D_MODEL + col] = v1;
            } else if (OM == 1) {
                __half* C = (__half*)Cv;
                *(__half2*)(C + (size_t)row * D_MODEL + col) =
                    __floats2half2_rn(v0.x, v0.y);
                *(__half2*)(C + (size_t)(row + 8) * D_MODEL + col) =
                    __floats2half2_rn(v1.x, v1.y);
            } else {
                __half* C = (__half*)Cv;
                const int b0i = row >> 11, tl0 = row & 2047;
                const int b1i = (row + 8) >> 11, tl1 = (row + 8) & 2047;
                C[((size_t)b0i * D_MODEL + col)     * SEQ + tl0] = __float2half_rn(v0.x);
                C[((size_t)b0i * D_MODEL + col + 1) * SEQ + tl0] = __float2half_rn(v0.y);
                C[((size_t)b1i * D_MODEL + col)     * SEQ + tl1] = __float2half_rn(v1.x);
                C[((size_t)b1i * D_MODEL + col + 1) * SEQ + tl1] = __float2half_rn(v1.y);
            }
        }
    }
}

// ---------------------------------------------------------------------------
// Flash attention (R13/14, unchanged): fp16 mma.m16n8k16, fp32 softmax.
// ---------------------------------------------------------------------------
#define HS 72
#define NTILES (SEQ / 64)
#define ATTN_SMEM ((128*HS + 2*64*HS + 2*64*HS) * (int)sizeof(__half))  // 55296

__global__ __launch_bounds__(256, 2) void attn_h(
    const __half* __restrict__ Qb, const __half* __restrict__ Kb,
    const __half* __restrict__ Vt, __half* __restrict__ Ob)
{
    extern __shared__ __half smh[];
    __half* Ps   = smh;                      // [128][HS]  (Q staging, then P)
    __half* Kbuf = Ps + 128 * HS;            // [2][64][HS]
    __half* Vbuf = Kbuf + 2 * 64 * HS;       // [2][64][HS]

    const int qt = blockIdx.x, h = blockIdx.y, b = blockIdx.z;
    const int t = threadIdx.x, w = t >> 5, lane = t & 31;
    const int g4 = lane >> 2, q4 = lane & 3;
    const int base_q = b * SEQ + qt * 128;
    const int hcol = h * HEAD_DIM;

    const int koff = ((lane & 7) + ((lane >> 4) << 3)) * HS + ((lane >> 3) & 1) * 8;
    const int poff = (lane & 15) * HS + (lane >> 4) * 8;

    const __half* Vbase = Vt + ((size_t)b * D_MODEL + hcol) * SEQ;

    {
        #pragma unroll
        for (int i = 0; i < 2; i++) {
            const int cid = t + i * 256;
            const int row = cid >> 3, seg = (cid & 7) * 8;
            cp_async16(&Kbuf[row * HS + seg],
                       Kb + (size_t)(b * SEQ + row) * D_MODEL + hcol + seg);
            cp_async16(&Vbuf[row * HS + seg],
                       Vbase + (size_t)row * SEQ + seg);
        }
    }
    CP_COMMIT();

    {
        const int r = t >> 1;
        const int c0 = (t & 1) * 32;
        #pragma unroll
        for (int i = 0; i < 4; i++)
            *(float4*)&Ps[r * HS + c0 + i * 8] =
                *(const float4*)(Qb + (size_t)(base_q + r) * D_MODEL + hcol + c0 + i * 8);
    }
    __syncwarp();

    unsigned qa[4][4];
    {
        const __half* qB = Ps + (w * 16) * HS + poff;
        #pragma unroll
        for (int kk = 0; kk < 4; kk++)
            ldsm4(qa[kk][0], qa[kk][1], qa[kk][2], qa[kk][3], qB + kk * 16);
    }
    __syncwarp();

    float of[8][4];
    #pragma unroll
    for (int n = 0; n < 8; n++)
        of[n][0] = of[n][1] = of[n][2] = of[n][3] = 0.f;
    float m0r = -1e30f, m1r = -1e30f, l0r = 0.f, l1r = 0.f;

    for (int jt = 0; jt < NTILES; jt++) {
        __half* Kc = Kbuf + (jt & 1) * 64 * HS;
        __half* Vc = Vbuf + (jt & 1) * 64 * HS;

        if (jt + 1 < NTILES) {
            __half* Kn = Kbuf + ((jt + 1) & 1) * 64 * HS;
            __half* Vn = Vbuf + ((jt + 1) & 1) * 64 * HS;
            const int tok0 = (jt + 1) * 64;
            #pragma unroll
            for (int i = 0; i < 2; i++) {
                const int cid = t + i * 256;
                const int row = cid >> 3, seg = (cid & 7) * 8;
                cp_async16(&Kn[row * HS + seg],
                           Kb + (size_t)(b * SEQ + tok0 + row) * D_MODEL + hcol + seg);
                cp_async16(&Vn[row * HS + seg],
                           Vbase + (size_t)row * SEQ + tok0 + seg);
            }
        }
        CP_COMMIT();
        CP_WAIT1();
        __syncthreads();

        float sfr[8][4];
        #pragma unroll
        for (int n = 0; n < 8; n++)
            sfr[n][0] = sfr[n][1] = sfr[n][2] = sfr[n][3] = 0.f;
        {
            const __half* kB = Kc + koff;
            #pragma unroll
            for (int kk = 0; kk < 4; kk++) {
                #pragma unroll
                for (int jp = 0; jp < 4; jp++) {
                    unsigned rb[4];
                    ldsm4(rb[0], rb[1], rb[2], rb[3], kB + jp * 16 * HS + kk * 16);
                    mma16h(sfr[jp * 2],     qa[kk], rb[0], rb[1]);
                    mma16h(sfr[jp * 2 + 1], qa[kk], rb[2], rb[3]);
                }
            }
        }

        float mx0 = -1e30f, mx1 = -1e30f;
        #pragma unroll
        for (int n = 0; n < 8; n++) {
            mx0 = fmaxf(mx0, fmaxf(sfr[n][0], sfr[n][1]));
            mx1 = fmaxf(mx1, fmaxf(sfr[n][2], sfr[n][3]));
        }
        mx0 = fmaxf(mx0, __shfl_xor_sync(0xffffffffu, mx0, 1));
        mx0 = fmaxf(mx0, __shfl_xor_sync(0xffffffffu, mx0, 2));
        mx1 = fmaxf(mx1, __shfl_xor_sync(0xffffffffu, mx1, 1));
        mx1 = fmaxf(mx1, __shfl_xor_sync(0xffffffffu, mx1, 2));

        const float mn0 = fmaxf(m0r, mx0);
        const float mn1 = fmaxf(m1r, mx1);
        const float a0 = __expf(m0r - mn0);
        const float a1 = __expf(m1r - mn1);
        m0r = mn0; m1r = mn1;

        float s0 = 0.f, s1 = 0.f;
        #pragma unroll
        for (int n = 0; n < 8; n++) {
            sfr[n][0] = __expf(sfr[n][0] - mn0);
            sfr[n][1] = __expf(sfr[n][1] - mn0);
            sfr[n][2] = __expf(sfr[n][2] - mn1);
            sfr[n][3] = __expf(sfr[n][3] - mn1);
            s0 += sfr[n][0] + sfr[n][1];
            s1 += sfr[n][2] + sfr[n][3];
            of[n][0] *= a0; of[n][1] *= a0;
            of[n][2] *= a1; of[n][3] *= a1;
            *(__half2*)&Ps[(w * 16 + g4)     * HS + n * 8 + 2 * q4] =
                __floats2half2_rn(sfr[n][0], sfr[n][1]);
            *(__half2*)&Ps[(w * 16 + g4 + 8) * HS + n * 8 + 2 * q4] =
                __floats2half2_rn(sfr[n][2], sfr[n][3]);
        }
        s0 += __shfl_xor_sync(0xffffffffu, s0, 1);
        s0 += __shfl_xor_sync(0xffffffffu, s0, 2);
        s1 += __shfl_xor_sync(0xffffffffu, s1, 1);
        s1 += __shfl_xor_sync(0xffffffffu, s1, 2);
        l0r = l0r * a0 + s0;
        l1r = l1r * a1 + s1;
        __syncwarp();

        {
            const __half* pB = Ps + (w * 16) * HS + poff;
            const __half* vB = Vc + koff;
            #pragma unroll
            for (int kk = 0; kk < 4; kk++) {
                unsigned pa[4];
                ldsm4(pa[0], pa[1], pa[2], pa[3], pB + kk * 16);
                #pragma unroll
                for (int jp = 0; jp < 4; jp++) {
                    unsigned rb[4];
                    ldsm4(rb[0], rb[1], rb[2], rb[3], vB + jp * 16 * HS + kk * 16);
                    mma16h(of[jp * 2],     pa, rb[0], rb[1]);
                    mma16h(of[jp * 2 + 1], pa, rb[2], rb[3]);
                }
            }
        }
        __syncwarp();
        __syncthreads();
    }

    const float inv0 = 1.f / l0r;
    const float inv1 = 1.f / l1r;
    const int r0 = base_q + w * 16 + g4;
    #pragma unroll
    for (int n = 0; n < 8; n++) {
        const int c = hcol + n * 8 + 2 * q4;
        *(__half2*)(Ob + (size_t)r0 * D_MODEL + c) =
            __floats2half2_rn(of[n][0] * inv0, of[n][1] * inv0);
        *(__half2*)(Ob + (size_t)(r0 + 8) * D_MODEL + c) =
            __floats2half2_rn(of[n][2] * inv1, of[n][3] * inv1);
    }
}

// ---------------------------------------------------------------------------
extern "C" void kernel_launch(void* const* d_in, const int* in_sizes, int n_in,
                              void* d_out, int out_size)
{
    const float* query = (const float*)d_in[0];
    const float* key   = (const float*)d_in[1];
    const float* value = (const float*)d_in[2];
    const float* Wq    = (const float*)d_in[3];
    const float* bq    = (const float*)d_in[4];
    const float* Wk    = (const float*)d_in[5];
    const float* bk    = (const float*)d_in[6];
    const float* Wv    = (const float*)d_in[7];
    const float* bv    = (const float*)d_in[8];
    const float* Wo    = (const float*)d_in[9];
    const float* bo    = (const float*)d_in[10];
    float* out = (float*)d_out;

    __half *pQ, *pK, *pVt, *pA;
    __half *hXq, *hXk, *hXv, *hWq, *hWk, *hWv, *hWo;
    cudaGetSymbolAddress((void**)&pQ, g_Q);
    cudaGetSymbolAddress((void**)&pK, g_K);
    cudaGetSymbolAddress((void**)&pVt, g_Vt);
    cudaGetSymbolAddress((void**)&pA, g_Attn);
    cudaGetSymbolAddress((void**)&hXq, g_hXq);
    cudaGetSymbolAddress((void**)&hXk, g_hXk);
    cudaGetSymbolAddress((void**)&hXv, g_hXv);
    cudaGetSymbolAddress((void**)&hWq, g_hWq);
    cudaGetSymbolAddress((void**)&hWk, g_hWk);
    cudaGetSymbolAddress((void**)&hWv, g_hWv);
    cudaGetSymbolAddress((void**)&hWo, g_hWo);

    cudaFuncSetAttribute((const void*)gemm_hcp<0>,
                         cudaFuncAttributeMaxDynamicSharedMemorySize, GEMMH_SMEM);
    cudaFuncSetAttribute((const void*)gemm_hcp<1>,
                         cudaFuncAttributeMaxDynamicSharedMemorySize, GEMMH_SMEM);
    cudaFuncSetAttribute((const void*)gemm_hcp<2>,
                         cudaFuncAttributeMaxDynamicSharedMemorySize, GEMMH_SMEM);
    cudaFuncSetAttribute((const void*)attn_h,
                         cudaFuncAttributeMaxDynamicSharedMemorySize, ATTN_SMEM);

    // --- f32 -> f16 pre-conversion (single launch, z = tensor id) ---
    dim3 cg((MTOT * D_MODEL / 8) / 256, 1, 7);      // (2048, 1, 7)
    f2h_all<<<cg, 256>>>(query, key, value, Wq, Wk, Wv, Wo,
                         hXq, hXk, hXv, hWq, hWk, hWv, hWo);

    dim3 gemm_grid(D_MODEL / 128, MTOT / 128);   // (8, 32)
    const float qscale = 0.125f;                 // 1/sqrt(64)

    gemm_hcp<1><<<gemm_grid, 256, GEMMH_SMEM>>>(hXq, hWq, bq, qscale, pQ);
    gemm_hcp<1><<<gemm_grid, 256, GEMMH_SMEM>>>(hXk, hWk, bk, 1.f,    pK);
    gemm_hcp<2><<<gemm_grid, 256, GEMMH_SMEM>>>(hXv, hWv, bv, 1.f,    pVt);

    dim3 attn_grid(SEQ / 128, NHEAD, BATCH);     // (16, 16, 2)
    attn_h<<<attn_grid, 256, ATTN_SMEM>>>(pQ, pK, pVt, pA);

    gemm_hcp<0><<<gemm_grid, 256, GEMMH_SMEM>>>(pA, hWo, bo, 1.f, out);
}